// round 1
// baseline (speedup 1.0000x reference)
#include <cuda_runtime.h>

#define N_NODES 50000
#define N_EDGES 800000
#define ET (N_EDGES + N_NODES)   // edges + self loops = 850000
#define IN_CH 128
#define H1 8
#define C1 64
#define F1 (H1 * C1)             // 512
#define NEG_SLOPE 0.2f

// ---------------- scratch (static device globals; no allocation) ------------
__device__ float g_h1[N_NODES * F1];      // x @ W1           (102.4 MB)
__device__ float g_act[N_NODES * F1];     // elu(agg1 + b1)   (102.4 MB)
__device__ float g_as1[N_NODES * H1];
__device__ float g_ad1[N_NODES * H1];
__device__ float g_h2[N_NODES * 2];
__device__ float g_as2[N_NODES];
__device__ float g_ad2[N_NODES];
__device__ int   g_deg[N_NODES];
__device__ int   g_off[N_NODES + 1];
__device__ int   g_cur[N_NODES];
__device__ int   g_csr_src[ET];

// ---------------- CSR build -------------------------------------------------
__global__ void k_init_deg() {
    int i = blockIdx.x * blockDim.x + threadIdx.x;
    if (i < N_NODES) g_deg[i] = 1;   // self loop
}

__global__ void k_count(const int* __restrict__ ei) {
    int e = blockIdx.x * blockDim.x + threadIdx.x;
    if (e < N_EDGES) atomicAdd(&g_deg[ei[N_EDGES + e]], 1);
}

__global__ void k_scan() {
    __shared__ int sh[1024];
    int t = threadIdx.x;
    int carry = 0;
    for (int base = 0; base < N_NODES; base += 1024) {
        int i = base + t;
        int v = (i < N_NODES) ? g_deg[i] : 0;
        sh[t] = v;
        __syncthreads();
        #pragma unroll
        for (int off = 1; off < 1024; off <<= 1) {
            int add = (t >= off) ? sh[t - off] : 0;
            __syncthreads();
            sh[t] += add;
            __syncthreads();
        }
        if (i < N_NODES) {
            int excl = carry + sh[t] - v;
            g_off[i] = excl;
            g_cur[i] = excl;
        }
        carry += sh[1023];
        __syncthreads();
    }
    if (t == 0) g_off[N_NODES] = carry;   // = ET
}

__global__ void k_scatter(const int* __restrict__ ei) {
    int e = blockIdx.x * blockDim.x + threadIdx.x;
    if (e >= ET) return;
    int src, dst;
    if (e < N_EDGES) { src = ei[e]; dst = ei[N_EDGES + e]; }
    else             { src = dst = e - N_EDGES; }
    int pos = atomicAdd(&g_cur[dst], 1);
    g_csr_src[pos] = src;
}

// ---------------- GEMM1: g_h1 = X[50000,128] @ W1[128,512] ------------------
__global__ void __launch_bounds__(256) k_gemm1(const float* __restrict__ X,
                                               const float* __restrict__ W) {
    __shared__ float As[32][128 + 4];
    __shared__ float Bs[32][128 + 4];
    int tid = threadIdx.x;
    int bm = blockIdx.x * 128, bn = blockIdx.y * 128;
    int tx = tid & 15, ty = tid >> 4;
    float acc[8][8] = {};
    for (int k0 = 0; k0 < IN_CH; k0 += 32) {
        #pragma unroll
        for (int i = 0; i < 4; i++) {                    // A tile: 128 rows x 32 k
            int idx = tid + i * 256;                     // 0..1023 float4s
            int r = idx >> 3;
            int kq = idx & 7;
            int row = bm + r;
            float4 v = make_float4(0.f, 0.f, 0.f, 0.f);
            if (row < N_NODES)
                v = *(const float4*)&X[row * IN_CH + k0 + kq * 4];
            As[kq * 4 + 0][r] = v.x;
            As[kq * 4 + 1][r] = v.y;
            As[kq * 4 + 2][r] = v.z;
            As[kq * 4 + 3][r] = v.w;
        }
        #pragma unroll
        for (int i = 0; i < 4; i++) {                    // B tile: 32 k x 128 cols
            int idx = tid + i * 256;
            int k = idx >> 5;
            int cq = idx & 31;
            float4 v = *(const float4*)&W[(k0 + k) * F1 + bn + cq * 4];
            *(float4*)&Bs[k][cq * 4] = v;
        }
        __syncthreads();
        #pragma unroll
        for (int k = 0; k < 32; k++) {
            float a[8], b[8];
            *(float4*)&a[0] = *(const float4*)&As[k][ty * 8];
            *(float4*)&a[4] = *(const float4*)&As[k][ty * 8 + 4];
            *(float4*)&b[0] = *(const float4*)&Bs[k][tx * 8];
            *(float4*)&b[4] = *(const float4*)&Bs[k][tx * 8 + 4];
            #pragma unroll
            for (int i = 0; i < 8; i++)
                #pragma unroll
                for (int j = 0; j < 8; j++)
                    acc[i][j] += a[i] * b[j];
        }
        __syncthreads();
    }
    #pragma unroll
    for (int i = 0; i < 8; i++) {
        int row = bm + ty * 8 + i;
        if (row < N_NODES) {
            *(float4*)&g_h1[row * F1 + bn + tx * 8] =
                make_float4(acc[i][0], acc[i][1], acc[i][2], acc[i][3]);
            *(float4*)&g_h1[row * F1 + bn + tx * 8 + 4] =
                make_float4(acc[i][4], acc[i][5], acc[i][6], acc[i][7]);
        }
    }
}

// ---------------- per-node attention scores layer 1 -------------------------
__global__ void k_scores1(const float* __restrict__ asrc,
                          const float* __restrict__ adst) {
    int gw = (blockIdx.x * blockDim.x + threadIdx.x) >> 5;
    int lane = threadIdx.x & 31;
    if (gw >= N_NODES) return;
    const float4* hp = (const float4*)g_h1 + (size_t)gw * (F1 / 4);
    const float4* ap = (const float4*)asrc;
    const float4* bp = (const float4*)adst;
    float s = 0.f, d = 0.f;
    #pragma unroll
    for (int q = 0; q < 4; q++) {
        float4 h = hp[lane * 4 + q];
        float4 a = ap[lane * 4 + q];
        float4 b = bp[lane * 4 + q];
        s += h.x * a.x + h.y * a.y + h.z * a.z + h.w * a.w;
        d += h.x * b.x + h.y * b.y + h.z * b.z + h.w * b.w;
    }
    s += __shfl_xor_sync(0xffffffffu, s, 1);
    s += __shfl_xor_sync(0xffffffffu, s, 2);
    d += __shfl_xor_sync(0xffffffffu, d, 1);
    d += __shfl_xor_sync(0xffffffffu, d, 2);
    if ((lane & 3) == 0) {
        int hd = lane >> 2;
        g_as1[gw * H1 + hd] = s;
        g_ad1[gw * H1 + hd] = d;
    }
}

// ---------------- layer-1 softmax + aggregation + bias + elu ----------------
// One 128-thread block per destination node. Thread t owns channels
// [t*4, t*4+4) => head t/16. Two passes over the CSR row: (A) max, (C)
// fused exp-weight / denominator / feature accumulation. No atomics.
__global__ void __launch_bounds__(128) k_agg1(const float* __restrict__ b1) {
    int n = blockIdx.x;
    int t = threadIdx.x;
    int start = g_off[n], end = g_off[n + 1];
    int ht = t >> 4;
    float adn = g_ad1[n * H1 + ht];

    float m = -1e30f;
    for (int j = start; j < end; j++) {
        int src = g_csr_src[j];
        float e = g_as1[src * H1 + ht] + adn;
        e = (e > 0.f) ? e : NEG_SLOPE * e;
        m = fmaxf(m, e);
    }

    float den = 0.f;
    float ax = 0.f, ay = 0.f, az = 0.f, aw = 0.f;
    const float4* h4 = (const float4*)g_h1;
    for (int j = start; j < end; j++) {
        int src = g_csr_src[j];
        float e = g_as1[src * H1 + ht] + adn;
        e = (e > 0.f) ? e : NEG_SLOPE * e;
        float w = __expf(e - m);
        den += w;
        float4 hv = h4[(size_t)src * (F1 / 4) + t];
        ax += w * hv.x; ay += w * hv.y; az += w * hv.z; aw += w * hv.w;
    }
    float inv = 1.f / den;
    float4 bv = ((const float4*)b1)[t];
    float o0 = ax * inv + bv.x;
    float o1 = ay * inv + bv.y;
    float o2 = az * inv + bv.z;
    float o3 = aw * inv + bv.w;
    // ELU
    o0 = (o0 > 0.f) ? o0 : (__expf(o0) - 1.f);
    o1 = (o1 > 0.f) ? o1 : (__expf(o1) - 1.f);
    o2 = (o2 > 0.f) ? o2 : (__expf(o2) - 1.f);
    o3 = (o3 > 0.f) ? o3 : (__expf(o3) - 1.f);
    ((float4*)g_act)[(size_t)n * (F1 / 4) + t] = make_float4(o0, o1, o2, o3);
}

// ---------------- layer-2 features + scores (warp per node) -----------------
__global__ void k_l2(const float* __restrict__ W2,
                     const float* __restrict__ asrc2,
                     const float* __restrict__ adst2) {
    int gw = (blockIdx.x * blockDim.x + threadIdx.x) >> 5;
    int lane = threadIdx.x & 31;
    if (gw >= N_NODES) return;
    const float* hp = g_act + (size_t)gw * F1;
    float a0 = 0.f, a1 = 0.f;
    #pragma unroll
    for (int q = 0; q < 16; q++) {
        int c = q * 32 + lane;
        float v = hp[c];
        a0 += v * W2[c * 2 + 0];
        a1 += v * W2[c * 2 + 1];
    }
    #pragma unroll
    for (int off = 16; off; off >>= 1) {
        a0 += __shfl_xor_sync(0xffffffffu, a0, off);
        a1 += __shfl_xor_sync(0xffffffffu, a1, off);
    }
    if (lane == 0) {
        g_h2[gw * 2 + 0] = a0;
        g_h2[gw * 2 + 1] = a1;
        g_as2[gw] = a0 * asrc2[0] + a1 * asrc2[1];
        g_ad2[gw] = a0 * adst2[0] + a1 * adst2[1];
    }
}

// ---------------- layer-2 softmax + aggregation (warp per node) -------------
__global__ void k_agg2(const float* __restrict__ b2, float* __restrict__ out) {
    int gw = (blockIdx.x * blockDim.x + threadIdx.x) >> 5;
    int lane = threadIdx.x & 31;
    if (gw >= N_NODES) return;
    int start = g_off[gw], end = g_off[gw + 1];
    float adn = g_ad2[gw];

    float m = -1e30f;
    for (int j = start + lane; j < end; j += 32) {
        int src = g_csr_src[j];
        float e = g_as2[src] + adn;
        e = (e > 0.f) ? e : NEG_SLOPE * e;
        m = fmaxf(m, e);
    }
    #pragma unroll
    for (int off = 16; off; off >>= 1)
        m = fmaxf(m, __shfl_xor_sync(0xffffffffu, m, off));

    float den = 0.f, a0 = 0.f, a1 = 0.f;
    for (int j = start + lane; j < end; j += 32) {
        int src = g_csr_src[j];
        float e = g_as2[src] + adn;
        e = (e > 0.f) ? e : NEG_SLOPE * e;
        float w = __expf(e - m);
        den += w;
        a0 += w * g_h2[src * 2 + 0];
        a1 += w * g_h2[src * 2 + 1];
    }
    #pragma unroll
    for (int off = 16; off; off >>= 1) {
        den += __shfl_xor_sync(0xffffffffu, den, off);
        a0  += __shfl_xor_sync(0xffffffffu, a0, off);
        a1  += __shfl_xor_sync(0xffffffffu, a1, off);
    }
    if (lane == 0) {
        float inv = 1.f / den;
        out[gw * 2 + 0] = a0 * inv + b2[0];
        out[gw * 2 + 1] = a1 * inv + b2[1];
    }
}

// ---------------- launcher ---------------------------------------------------
extern "C" void kernel_launch(void* const* d_in, const int* in_sizes, int n_in,
                              void* d_out, int out_size) {
    const float* x      = (const float*)d_in[0];
    const int*   ei     = (const int*)  d_in[1];
    const float* W1     = (const float*)d_in[2];
    const float* a_src1 = (const float*)d_in[3];
    const float* a_dst1 = (const float*)d_in[4];
    const float* b1     = (const float*)d_in[5];
    const float* W2     = (const float*)d_in[6];
    const float* a_src2 = (const float*)d_in[7];
    const float* a_dst2 = (const float*)d_in[8];
    const float* b2     = (const float*)d_in[9];
    float* out = (float*)d_out;

    // CSR build
    k_init_deg<<<(N_NODES + 255) / 256, 256>>>();
    k_count<<<(N_EDGES + 255) / 256, 256>>>(ei);
    k_scan<<<1, 1024>>>();
    k_scatter<<<(ET + 255) / 256, 256>>>(ei);

    // layer 1
    dim3 gemm_grid((N_NODES + 127) / 128, F1 / 128);
    k_gemm1<<<gemm_grid, 256>>>(x, W1);
    k_scores1<<<(N_NODES + 7) / 8, 256>>>(a_src1, a_dst1);
    k_agg1<<<N_NODES, 128>>>(b1);

    // layer 2
    k_l2<<<(N_NODES + 7) / 8, 256>>>(W2, a_src2, a_dst2);
    k_agg2<<<(N_NODES + 7) / 8, 256>>>(b2, out);
}

// round 3
// speedup vs baseline: 1.2319x; 1.2319x over previous
#include <cuda_runtime.h>
#include <cuda_bf16.h>
#include <cstdint>

#define N_NODES 50000
#define N_EDGES 800000
#define ET (N_EDGES + N_NODES)   // edges + self loops = 850000
#define IN_CH 128
#define H1 8
#define C1 64
#define F1 (H1 * C1)             // 512
#define NEG_SLOPE 0.2f

// ---------------- scratch (static device globals; no allocation) ------------
__device__ float g_h1[N_NODES * F1];      // x @ W1           (102.4 MB)
__device__ float g_act[N_NODES * F1];     // elu(agg1 + b1)   (102.4 MB)
__device__ float g_as1[N_NODES * H1];
__device__ float g_ad1[N_NODES * H1];
__device__ float g_h2[N_NODES * 2];
__device__ float g_as2[N_NODES];
__device__ float g_ad2[N_NODES];
__device__ int   g_deg[N_NODES];
__device__ int   g_off[N_NODES + 1];
__device__ int   g_cur[N_NODES];
__device__ int   g_csr_src[ET];

// bf16 split operands for the tensor-core GEMM
__device__ __nv_bfloat16 g_ah[N_NODES * IN_CH];   // hi(x)     [m][k]
__device__ __nv_bfloat16 g_al[N_NODES * IN_CH];   // lo(x)
__device__ __nv_bfloat16 g_bh[F1 * IN_CH];        // hi(W1^T)  [n][k]
__device__ __nv_bfloat16 g_bl[F1 * IN_CH];        // lo(W1^T)

// ---------------- PTX helpers ------------------------------------------------
__device__ __forceinline__ uint32_t smem_u32(const void* p) {
    uint32_t a;
    asm("{ .reg .u64 t; cvta.to.shared.u64 t, %1; cvt.u32.u64 %0, t; }"
        : "=r"(a) : "l"(p));
    return a;
}

__device__ __forceinline__ void ldm_x4(uint32_t* r, uint32_t addr) {
    asm volatile("ldmatrix.sync.aligned.m8n8.x4.shared.b16 {%0,%1,%2,%3}, [%4];"
                 : "=r"(r[0]), "=r"(r[1]), "=r"(r[2]), "=r"(r[3]) : "r"(addr));
}

__device__ __forceinline__ void mma_bf16(float* d, const uint32_t* a,
                                         const uint32_t* b) {
    asm volatile("mma.sync.aligned.m16n8k16.row.col.f32.bf16.bf16.f32 "
                 "{%0,%1,%2,%3}, {%4,%5,%6,%7}, {%8,%9}, {%0,%1,%2,%3};"
                 : "+f"(d[0]), "+f"(d[1]), "+f"(d[2]), "+f"(d[3])
                 : "r"(a[0]), "r"(a[1]), "r"(a[2]), "r"(a[3]),
                   "r"(b[0]), "r"(b[1]));
}

// ---------------- CSR build -------------------------------------------------
__global__ void k_init_deg() {
    int i = blockIdx.x * blockDim.x + threadIdx.x;
    if (i < N_NODES) g_deg[i] = 1;   // self loop
}

__global__ void k_count(const int* __restrict__ ei) {
    int e = blockIdx.x * blockDim.x + threadIdx.x;
    if (e < N_EDGES) atomicAdd(&g_deg[ei[N_EDGES + e]], 1);
}

__global__ void k_scan() {
    __shared__ int sh[1024];
    int t = threadIdx.x;
    int carry = 0;
    for (int base = 0; base < N_NODES; base += 1024) {
        int i = base + t;
        int v = (i < N_NODES) ? g_deg[i] : 0;
        sh[t] = v;
        __syncthreads();
        #pragma unroll
        for (int off = 1; off < 1024; off <<= 1) {
            int add = (t >= off) ? sh[t - off] : 0;
            __syncthreads();
            sh[t] += add;
            __syncthreads();
        }
        if (i < N_NODES) {
            int excl = carry + sh[t] - v;
            g_off[i] = excl;
            g_cur[i] = excl;
        }
        carry += sh[1023];
        __syncthreads();
    }
    if (t == 0) g_off[N_NODES] = carry;   // = ET
}

__global__ void k_scatter(const int* __restrict__ ei) {
    int e = blockIdx.x * blockDim.x + threadIdx.x;
    if (e >= ET) return;
    int src, dst;
    if (e < N_EDGES) { src = ei[e]; dst = ei[N_EDGES + e]; }
    else             { src = dst = e - N_EDGES; }
    int pos = atomicAdd(&g_cur[dst], 1);
    g_csr_src[pos] = src;
}

// ---------------- operand prep: bf16 error-free split ------------------------
__global__ void k_prep_a(const float* __restrict__ x) {
    int idx = blockIdx.x * blockDim.x + threadIdx.x;
    if (idx >= N_NODES * IN_CH) return;
    float v = x[idx];
    __nv_bfloat16 hi = __float2bfloat16(v);
    __nv_bfloat16 lo = __float2bfloat16(v - __bfloat162float(hi));
    g_ah[idx] = hi;
    g_al[idx] = lo;
}

__global__ void k_prep_b(const float* __restrict__ W) {
    int idx = blockIdx.x * blockDim.x + threadIdx.x;   // over 512*128
    if (idx >= F1 * IN_CH) return;
    int n = idx & (F1 - 1);
    int k = idx >> 9;
    float v = W[k * F1 + n];                           // coalesced read
    __nv_bfloat16 hi = __float2bfloat16(v);
    __nv_bfloat16 lo = __float2bfloat16(v - __bfloat162float(hi));
    g_bh[n * IN_CH + k] = hi;
    g_bl[n * IN_CH + k] = lo;
}

// ---------------- mma.sync GEMM: g_h1 = X @ W1  (+ fused attention scores) ---
// Grid (391, 4). CTA tile M=128 x N=128; 8 warps as 4(M) x 2(N), warp tile
// 32x64. K staged in 64-chunks: 6 stages = 3 split terms x 2 k-halves:
//   term 0: Xh*Wh   term 1: Xh*Wl   term 2: Xl*Wh
#define AS_STRIDE 72            // halves per row (144B: 16B-aligned, swizzle-free)

__global__ void __launch_bounds__(256) k_gemm_mma(
        const float* __restrict__ asrc, const float* __restrict__ adst) {
    __shared__ __nv_bfloat16 As[128 * AS_STRIDE];
    __shared__ __nv_bfloat16 Bs[128 * AS_STRIDE];
    __shared__ float scs[256];    // [0,128): a_src cols, [128,256): a_dst cols

    int tid = threadIdx.x;
    int lane = tid & 31, wid = tid >> 5;
    int wm = wid & 3, wn = wid >> 2;
    int bm = blockIdx.x * 128;
    int nb = blockIdx.y;                 // N block: cols [nb*128, nb*128+128)

    scs[tid] = (tid < 128) ? asrc[nb * 128 + tid] : adst[nb * 128 + tid - 128];

    uint32_t sA = smem_u32(As), sB = smem_u32(Bs);
    float acc[2][8][4];
    #pragma unroll
    for (int i = 0; i < 2; i++)
        #pragma unroll
        for (int j = 0; j < 8; j++)
            #pragma unroll
            for (int q = 0; q < 4; q++) acc[i][j][q] = 0.f;

    // precomputed ldmatrix lane addresses (halves offsets)
    uint32_t a_off0 = (uint32_t)((wm * 32 + (lane & 15)) * AS_STRIDE +
                                 (lane >> 4) * 8) * 2;
    uint32_t b_off0 = (uint32_t)(((lane >> 4) * 8 + (lane & 7)) * AS_STRIDE +
                                 ((lane >> 3) & 1) * 8) * 2;

    #pragma unroll 1
    for (int s = 0; s < 6; s++) {
        int term = s >> 1, kof = (s & 1) * 64;
        const __nv_bfloat16* pa = (term == 2) ? g_al : g_ah;
        const __nv_bfloat16* pb = (term == 1) ? g_bl : g_bh;

        // A: 128 rows x 64 halves (1024 x 16B chunks)
        #pragma unroll
        for (int it = 0; it < 4; it++) {
            int idx = tid + it * 256;
            int r = idx >> 3, c = idx & 7;
            int grow = bm + r;
            uint4 v = make_uint4(0u, 0u, 0u, 0u);
            if (grow < N_NODES)
                v = *(const uint4*)(pa + (size_t)grow * IN_CH + kof + c * 8);
            *(uint4*)(As + r * AS_STRIDE + c * 8) = v;
        }
        // B: 128 n-rows x 64 halves
        #pragma unroll
        for (int it = 0; it < 4; it++) {
            int idx = tid + it * 256;
            int r = idx >> 3, c = idx & 7;
            uint4 v = *(const uint4*)(pb + (size_t)(nb * 128 + r) * IN_CH +
                                      kof + c * 8);
            *(uint4*)(Bs + r * AS_STRIDE + c * 8) = v;
        }
        __syncthreads();

        #pragma unroll
        for (int ks = 0; ks < 4; ks++) {
            uint32_t af[2][4], bf[4][4];
            #pragma unroll
            for (int mt = 0; mt < 2; mt++)
                ldm_x4(af[mt], sA + a_off0 +
                       (uint32_t)(mt * 16 * AS_STRIDE + ks * 16) * 2);
            #pragma unroll
            for (int np = 0; np < 4; np++)
                ldm_x4(bf[np], sB + b_off0 +
                       (uint32_t)((wn * 64 + np * 16) * AS_STRIDE + ks * 16) * 2);
            #pragma unroll
            for (int mt = 0; mt < 2; mt++)
                #pragma unroll
                for (int np = 0; np < 4; np++) {
                    mma_bf16(acc[mt][np * 2 + 0], af[mt], &bf[np][0]);
                    mma_bf16(acc[mt][np * 2 + 1], af[mt], &bf[np][2]);
                }
        }
        __syncthreads();
    }

    // ---- epilogue: store h1 + fused per-head attention scores ----
    int ql = lane & 3, qr = lane >> 2;
    int head = nb * 2 + wn;

    // per-thread score-vector slices (16 cols this thread touches)
    float va[16], vd[16];
    #pragma unroll
    for (int nt = 0; nt < 8; nt++)
        #pragma unroll
        for (int j = 0; j < 2; j++) {
            int cw = wn * 64 + nt * 8 + ql * 2 + j;
            va[nt * 2 + j] = scs[cw];
            vd[nt * 2 + j] = scs[128 + cw];
        }

    #pragma unroll
    for (int mt = 0; mt < 2; mt++) {
        int row0 = bm + wm * 32 + mt * 16 + qr;
        float sa0 = 0.f, sd0 = 0.f, sa8 = 0.f, sd8 = 0.f;
        #pragma unroll
        for (int nt = 0; nt < 8; nt++) {
            float d0 = acc[mt][nt][0], d1 = acc[mt][nt][1];
            float d2 = acc[mt][nt][2], d3 = acc[mt][nt][3];
            sa0 += d0 * va[nt * 2] + d1 * va[nt * 2 + 1];
            sd0 += d0 * vd[nt * 2] + d1 * vd[nt * 2 + 1];
            sa8 += d2 * va[nt * 2] + d3 * va[nt * 2 + 1];
            sd8 += d2 * vd[nt * 2] + d3 * vd[nt * 2 + 1];
            int col = nb * 128 + wn * 64 + nt * 8 + ql * 2;
            if (row0 < N_NODES)
                *(float2*)(g_h1 + (size_t)row0 * F1 + col) = make_float2(d0, d1);
            if (row0 + 8 < N_NODES)
                *(float2*)(g_h1 + (size_t)(row0 + 8) * F1 + col) = make_float2(d2, d3);
        }
        // reduce across the quad (lanes sharing qr)
        #pragma unroll
        for (int o = 1; o <= 2; o <<= 1) {
            sa0 += __shfl_xor_sync(0xffffffffu, sa0, o);
            sd0 += __shfl_xor_sync(0xffffffffu, sd0, o);
            sa8 += __shfl_xor_sync(0xffffffffu, sa8, o);
            sd8 += __shfl_xor_sync(0xffffffffu, sd8, o);
        }
        if (ql == 0) {
            if (row0 < N_NODES) {
                g_as1[row0 * H1 + head] = sa0;
                g_ad1[row0 * H1 + head] = sd0;
            }
            if (row0 + 8 < N_NODES) {
                g_as1[(row0 + 8) * H1 + head] = sa8;
                g_ad1[(row0 + 8) * H1 + head] = sd8;
            }
        }
    }
}

// ---------------- layer-1 softmax + aggregation + bias + elu ----------------
__global__ void __launch_bounds__(128) k_agg1(const float* __restrict__ b1) {
    int n = blockIdx.x;
    int t = threadIdx.x;
    int start = g_off[n], end = g_off[n + 1];
    int ht = t >> 4;
    float adn = g_ad1[n * H1 + ht];

    float m = -1e30f;
    for (int j = start; j < end; j++) {
        int src = g_csr_src[j];
        float e = g_as1[src * H1 + ht] + adn;
        e = (e > 0.f) ? e : NEG_SLOPE * e;
        m = fmaxf(m, e);
    }

    float den = 0.f;
    float ax = 0.f, ay = 0.f, az = 0.f, aw = 0.f;
    const float4* h4 = (const float4*)g_h1;
    for (int j = start; j < end; j++) {
        int src = g_csr_src[j];
        float e = g_as1[src * H1 + ht] + adn;
        e = (e > 0.f) ? e : NEG_SLOPE * e;
        float w = __expf(e - m);
        den += w;
        float4 hv = h4[(size_t)src * (F1 / 4) + t];
        ax += w * hv.x; ay += w * hv.y; az += w * hv.z; aw += w * hv.w;
    }
    float inv = 1.f / den;
    float4 bv = ((const float4*)b1)[t];
    float o0 = ax * inv + bv.x;
    float o1 = ay * inv + bv.y;
    float o2 = az * inv + bv.z;
    float o3 = aw * inv + bv.w;
    o0 = (o0 > 0.f) ? o0 : (__expf(o0) - 1.f);
    o1 = (o1 > 0.f) ? o1 : (__expf(o1) - 1.f);
    o2 = (o2 > 0.f) ? o2 : (__expf(o2) - 1.f);
    o3 = (o3 > 0.f) ? o3 : (__expf(o3) - 1.f);
    ((float4*)g_act)[(size_t)n * (F1 / 4) + t] = make_float4(o0, o1, o2, o3);
}

// ---------------- layer-2 features + scores (warp per node) -----------------
__global__ void k_l2(const float* __restrict__ W2,
                     const float* __restrict__ asrc2,
                     const float* __restrict__ adst2) {
    int gw = (blockIdx.x * blockDim.x + threadIdx.x) >> 5;
    int lane = threadIdx.x & 31;
    if (gw >= N_NODES) return;
    const float* hp = g_act + (size_t)gw * F1;
    float a0 = 0.f, a1 = 0.f;
    #pragma unroll
    for (int q = 0; q < 16; q++) {
        int c = q * 32 + lane;
        float v = hp[c];
        a0 += v * W2[c * 2 + 0];
        a1 += v * W2[c * 2 + 1];
    }
    #pragma unroll
    for (int off = 16; off; off >>= 1) {
        a0 += __shfl_xor_sync(0xffffffffu, a0, off);
        a1 += __shfl_xor_sync(0xffffffffu, a1, off);
    }
    if (lane == 0) {
        g_h2[gw * 2 + 0] = a0;
        g_h2[gw * 2 + 1] = a1;
        g_as2[gw] = a0 * asrc2[0] + a1 * asrc2[1];
        g_ad2[gw] = a0 * adst2[0] + a1 * adst2[1];
    }
}

// ---------------- layer-2 softmax + aggregation (warp per node) -------------
__global__ void k_agg2(const float* __restrict__ b2, float* __restrict__ out) {
    int gw = (blockIdx.x * blockDim.x + threadIdx.x) >> 5;
    int lane = threadIdx.x & 31;
    if (gw >= N_NODES) return;
    int start = g_off[gw], end = g_off[gw + 1];
    float adn = g_ad2[gw];

    float m = -1e30f;
    for (int j = start + lane; j < end; j += 32) {
        int src = g_csr_src[j];
        float e = g_as2[src] + adn;
        e = (e > 0.f) ? e : NEG_SLOPE * e;
        m = fmaxf(m, e);
    }
    #pragma unroll
    for (int off = 16; off; off >>= 1)
        m = fmaxf(m, __shfl_xor_sync(0xffffffffu, m, off));

    float den = 0.f, a0 = 0.f, a1 = 0.f;
    for (int j = start + lane; j < end; j += 32) {
        int src = g_csr_src[j];
        float e = g_as2[src] + adn;
        e = (e > 0.f) ? e : NEG_SLOPE * e;
        float w = __expf(e - m);
        den += w;
        a0 += w * g_h2[src * 2 + 0];
        a1 += w * g_h2[src * 2 + 1];
    }
    #pragma unroll
    for (int off = 16; off; off >>= 1) {
        den += __shfl_xor_sync(0xffffffffu, den, off);
        a0  += __shfl_xor_sync(0xffffffffu, a0, off);
        a1  += __shfl_xor_sync(0xffffffffu, a1, off);
    }
    if (lane == 0) {
        float inv = 1.f / den;
        out[gw * 2 + 0] = a0 * inv + b2[0];
        out[gw * 2 + 1] = a1 * inv + b2[1];
    }
}

// ---------------- launcher ---------------------------------------------------
extern "C" void kernel_launch(void* const* d_in, const int* in_sizes, int n_in,
                              void* d_out, int out_size) {
    const float* x      = (const float*)d_in[0];
    const int*   ei     = (const int*)  d_in[1];
    const float* W1     = (const float*)d_in[2];
    const float* a_src1 = (const float*)d_in[3];
    const float* a_dst1 = (const float*)d_in[4];
    const float* b1     = (const float*)d_in[5];
    const float* W2     = (const float*)d_in[6];
    const float* a_src2 = (const float*)d_in[7];
    const float* a_dst2 = (const float*)d_in[8];
    const float* b2     = (const float*)d_in[9];
    float* out = (float*)d_out;

    // CSR build
    k_init_deg<<<(N_NODES + 255) / 256, 256>>>();
    k_count<<<(N_EDGES + 255) / 256, 256>>>(ei);
    k_scan<<<1, 1024>>>();
    k_scatter<<<(ET + 255) / 256, 256>>>(ei);

    // layer 1: bf16 split + tensor-core GEMM (+fused scores)
    k_prep_a<<<(N_NODES * IN_CH + 255) / 256, 256>>>(x);
    k_prep_b<<<(F1 * IN_CH + 255) / 256, 256>>>(W1);
    dim3 gg((N_NODES + 127) / 128, 4);
    k_gemm_mma<<<gg, 256>>>(a_src1, a_dst1);
    k_agg1<<<N_NODES, 128>>>(b1);

    // layer 2
    k_l2<<<(N_NODES + 7) / 8, 256>>>(W2, a_src2, a_dst2);
    k_agg2<<<(N_NODES + 7) / 8, 256>>>(b2, out);
}

// round 4
// speedup vs baseline: 1.3437x; 1.0907x over previous
#include <cuda_runtime.h>
#include <cuda_bf16.h>
#include <cstdint>

#define N_NODES 50000
#define N_EDGES 800000
#define ET (N_EDGES + N_NODES)   // edges + self loops = 850000
#define IN_CH 128
#define H1 8
#define C1 64
#define F1 (H1 * C1)             // 512
#define NEG_SLOPE 0.2f

// ---------------- scratch (static device globals; no allocation) ------------
__device__ float g_h1[N_NODES * F1];      // x @ W1           (102.4 MB)
__device__ float g_as1[N_NODES * H1];
__device__ float g_ad1[N_NODES * H1];
__device__ float g_h2[N_NODES * 2];
__device__ float g_as2[N_NODES];
__device__ float g_ad2[N_NODES];
__device__ int   g_deg[N_NODES];
__device__ int   g_off[N_NODES + 1];
__device__ int   g_cur[N_NODES];
__device__ int   g_csr_src[ET];

// bf16 split operands for the tensor-core GEMM
__device__ __nv_bfloat16 g_ah[N_NODES * IN_CH];   // hi(x)     [m][k]
__device__ __nv_bfloat16 g_al[N_NODES * IN_CH];   // lo(x)
__device__ __nv_bfloat16 g_bh[F1 * IN_CH];        // hi(W1^T)  [n][k]
__device__ __nv_bfloat16 g_bl[F1 * IN_CH];        // lo(W1^T)

// ---------------- PTX helpers ------------------------------------------------
__device__ __forceinline__ uint32_t smem_u32(const void* p) {
    uint32_t a;
    asm("{ .reg .u64 t; cvta.to.shared.u64 t, %1; cvt.u32.u64 %0, t; }"
        : "=r"(a) : "l"(p));
    return a;
}

__device__ __forceinline__ void ldm_x4(uint32_t* r, uint32_t addr) {
    asm volatile("ldmatrix.sync.aligned.m8n8.x4.shared.b16 {%0,%1,%2,%3}, [%4];"
                 : "=r"(r[0]), "=r"(r[1]), "=r"(r[2]), "=r"(r[3]) : "r"(addr));
}

__device__ __forceinline__ void mma_bf16(float* d, const uint32_t* a,
                                         const uint32_t* b) {
    asm volatile("mma.sync.aligned.m16n8k16.row.col.f32.bf16.bf16.f32 "
                 "{%0,%1,%2,%3}, {%4,%5,%6,%7}, {%8,%9}, {%0,%1,%2,%3};"
                 : "+f"(d[0]), "+f"(d[1]), "+f"(d[2]), "+f"(d[3])
                 : "r"(a[0]), "r"(a[1]), "r"(a[2]), "r"(a[3]),
                   "r"(b[0]), "r"(b[1]));
}

__device__ __forceinline__ void cp16(uint32_t dst, const void* src,
                                     uint32_t src_bytes) {
    asm volatile("cp.async.cg.shared.global [%0], [%1], 16, %2;"
                 :: "r"(dst), "l"(src), "r"(src_bytes));
}

// ---------------- CSR build -------------------------------------------------
__global__ void k_init_deg() {
    int i = blockIdx.x * blockDim.x + threadIdx.x;
    if (i < N_NODES) g_deg[i] = 1;   // self loop
}

__global__ void k_count(const int* __restrict__ ei) {
    int e = blockIdx.x * blockDim.x + threadIdx.x;
    if (e < N_EDGES) atomicAdd(&g_deg[ei[N_EDGES + e]], 1);
}

__global__ void k_scan() {
    __shared__ int sh[1024];
    int t = threadIdx.x;
    int carry = 0;
    for (int base = 0; base < N_NODES; base += 1024) {
        int i = base + t;
        int v = (i < N_NODES) ? g_deg[i] : 0;
        sh[t] = v;
        __syncthreads();
        #pragma unroll
        for (int off = 1; off < 1024; off <<= 1) {
            int add = (t >= off) ? sh[t - off] : 0;
            __syncthreads();
            sh[t] += add;
            __syncthreads();
        }
        if (i < N_NODES) {
            int excl = carry + sh[t] - v;
            g_off[i] = excl;
            g_cur[i] = excl;
        }
        carry += sh[1023];
        __syncthreads();
    }
    if (t == 0) g_off[N_NODES] = carry;   // = ET
}

__global__ void k_scatter(const int* __restrict__ ei) {
    int e = blockIdx.x * blockDim.x + threadIdx.x;
    if (e >= ET) return;
    int src, dst;
    if (e < N_EDGES) { src = ei[e]; dst = ei[N_EDGES + e]; }
    else             { src = dst = e - N_EDGES; }
    int pos = atomicAdd(&g_cur[dst], 1);
    g_csr_src[pos] = src;
}

// ---------------- operand prep: bf16 error-free split ------------------------
__global__ void k_prep_a(const float* __restrict__ x) {
    int idx = blockIdx.x * blockDim.x + threadIdx.x;
    if (idx >= N_NODES * IN_CH) return;
    float v = x[idx];
    __nv_bfloat16 hi = __float2bfloat16(v);
    __nv_bfloat16 lo = __float2bfloat16(v - __bfloat162float(hi));
    g_ah[idx] = hi;
    g_al[idx] = lo;
}

__global__ void k_prep_b(const float* __restrict__ W) {
    int idx = blockIdx.x * blockDim.x + threadIdx.x;   // over 512*128
    if (idx >= F1 * IN_CH) return;
    int n = idx & (F1 - 1);
    int k = idx >> 9;
    float v = W[k * F1 + n];                           // coalesced read
    __nv_bfloat16 hi = __float2bfloat16(v);
    __nv_bfloat16 lo = __float2bfloat16(v - __bfloat162float(hi));
    g_bh[n * IN_CH + k] = hi;
    g_bl[n * IN_CH + k] = lo;
}

// ---------------- mma.sync GEMM: g_h1 = X @ W1  (+ fused attention scores) ---
// Grid (391, 4). CTA tile M=128 x N=128; 8 warps as 4(M) x 2(N), warp tile
// 32x64. K staged in 64-chunks, cp.async double-buffered: 6 stages =
// 3 split terms x 2 k-halves:  term0 Xh*Wh, term1 Xh*Wl, term2 Xl*Wh.
#define AS_STRIDE 72              // halves per row (144B, 16B-aligned)
#define STG_BYTES (128 * AS_STRIDE * 2)          // 18432 per tile buffer
#define GEMM_SMEM (4 * STG_BYTES + 1024)         // A0 A1 B0 B1 + scs

__device__ __forceinline__ void prefetch_stage(int s, int tid, int bm, int nb,
                                               uint32_t sA, uint32_t sB) {
    int term = s >> 1, kof = (s & 1) * 64;
    const __nv_bfloat16* pa = (term == 2) ? g_al : g_ah;
    const __nv_bfloat16* pb = (term == 1) ? g_bl : g_bh;
    #pragma unroll
    for (int it = 0; it < 4; it++) {
        int idx = tid + it * 256;
        int r = idx >> 3, c = idx & 7;
        int grow = bm + r;
        int ok = grow < N_NODES;
        const void* gp = pa + (size_t)(ok ? grow : 0) * IN_CH + kof + c * 8;
        cp16(sA + (uint32_t)(r * AS_STRIDE + c * 8) * 2, gp, ok ? 16u : 0u);
    }
    #pragma unroll
    for (int it = 0; it < 4; it++) {
        int idx = tid + it * 256;
        int r = idx >> 3, c = idx & 7;
        const void* gp = pb + (size_t)(nb * 128 + r) * IN_CH + kof + c * 8;
        cp16(sB + (uint32_t)(r * AS_STRIDE + c * 8) * 2, gp, 16u);
    }
    asm volatile("cp.async.commit_group;" ::: "memory");
}

__global__ void __launch_bounds__(256) k_gemm_mma(
        const float* __restrict__ asrc, const float* __restrict__ adst) {
    extern __shared__ char dyn[];
    uint32_t base = smem_u32(dyn);
    uint32_t sAb[2] = {base, base + STG_BYTES};
    uint32_t sBb[2] = {base + 2 * STG_BYTES, base + 3 * STG_BYTES};
    float* scs = (float*)(dyn + 4 * STG_BYTES);   // [0,128) a_src, [128,256) a_dst

    int tid = threadIdx.x;
    int lane = tid & 31, wid = tid >> 5;
    int wm = wid & 3, wn = wid >> 2;
    int bm = blockIdx.x * 128;
    int nb = blockIdx.y;                 // N block: cols [nb*128, nb*128+128)

    scs[tid] = (tid < 128) ? asrc[nb * 128 + tid] : adst[nb * 128 + tid - 128];

    float acc[2][8][4];
    #pragma unroll
    for (int i = 0; i < 2; i++)
        #pragma unroll
        for (int j = 0; j < 8; j++)
            #pragma unroll
            for (int q = 0; q < 4; q++) acc[i][j][q] = 0.f;

    // ldmatrix lane base offsets (bytes)
    uint32_t a_off0 = (uint32_t)((wm * 32 + (lane & 15)) * AS_STRIDE +
                                 (lane >> 4) * 8) * 2;
    uint32_t b_off0 = (uint32_t)(((lane >> 4) * 8 + (lane & 7)) * AS_STRIDE +
                                 ((lane >> 3) & 1) * 8) * 2;

    prefetch_stage(0, tid, bm, nb, sAb[0], sBb[0]);

    #pragma unroll 1
    for (int s = 0; s < 6; s++) {
        if (s < 5) {
            prefetch_stage(s + 1, tid, bm, nb, sAb[(s + 1) & 1], sBb[(s + 1) & 1]);
            asm volatile("cp.async.wait_group 1;" ::: "memory");
        } else {
            asm volatile("cp.async.wait_group 0;" ::: "memory");
        }
        __syncthreads();

        uint32_t sA = sAb[s & 1], sB = sBb[s & 1];
        #pragma unroll
        for (int ks = 0; ks < 4; ks++) {
            uint32_t af[2][4], bf[4][4];
            #pragma unroll
            for (int mt = 0; mt < 2; mt++)
                ldm_x4(af[mt], sA + a_off0 +
                       (uint32_t)(mt * 16 * AS_STRIDE + ks * 16) * 2);
            #pragma unroll
            for (int np = 0; np < 4; np++)
                ldm_x4(bf[np], sB + b_off0 +
                       (uint32_t)((wn * 64 + np * 16) * AS_STRIDE + ks * 16) * 2);
            #pragma unroll
            for (int mt = 0; mt < 2; mt++)
                #pragma unroll
                for (int np = 0; np < 4; np++) {
                    mma_bf16(acc[mt][np * 2 + 0], af[mt], &bf[np][0]);
                    mma_bf16(acc[mt][np * 2 + 1], af[mt], &bf[np][2]);
                }
        }
        __syncthreads();
    }

    // ---- epilogue: store h1 + fused per-head attention scores ----
    int ql = lane & 3, qr = lane >> 2;
    int head = nb * 2 + wn;

    float va[16], vd[16];
    #pragma unroll
    for (int nt = 0; nt < 8; nt++)
        #pragma unroll
        for (int j = 0; j < 2; j++) {
            int cw = wn * 64 + nt * 8 + ql * 2 + j;
            va[nt * 2 + j] = scs[cw];
            vd[nt * 2 + j] = scs[128 + cw];
        }

    #pragma unroll
    for (int mt = 0; mt < 2; mt++) {
        int row0 = bm + wm * 32 + mt * 16 + qr;
        float sa0 = 0.f, sd0 = 0.f, sa8 = 0.f, sd8 = 0.f;
        #pragma unroll
        for (int nt = 0; nt < 8; nt++) {
            float d0 = acc[mt][nt][0], d1 = acc[mt][nt][1];
            float d2 = acc[mt][nt][2], d3 = acc[mt][nt][3];
            sa0 += d0 * va[nt * 2] + d1 * va[nt * 2 + 1];
            sd0 += d0 * vd[nt * 2] + d1 * vd[nt * 2 + 1];
            sa8 += d2 * va[nt * 2] + d3 * va[nt * 2 + 1];
            sd8 += d2 * vd[nt * 2] + d3 * vd[nt * 2 + 1];
            int col = nb * 128 + wn * 64 + nt * 8 + ql * 2;
            if (row0 < N_NODES)
                *(float2*)(g_h1 + (size_t)row0 * F1 + col) = make_float2(d0, d1);
            if (row0 + 8 < N_NODES)
                *(float2*)(g_h1 + (size_t)(row0 + 8) * F1 + col) = make_float2(d2, d3);
        }
        #pragma unroll
        for (int o = 1; o <= 2; o <<= 1) {
            sa0 += __shfl_xor_sync(0xffffffffu, sa0, o);
            sd0 += __shfl_xor_sync(0xffffffffu, sd0, o);
            sa8 += __shfl_xor_sync(0xffffffffu, sa8, o);
            sd8 += __shfl_xor_sync(0xffffffffu, sd8, o);
        }
        if (ql == 0) {
            if (row0 < N_NODES) {
                g_as1[row0 * H1 + head] = sa0;
                g_ad1[row0 * H1 + head] = sd0;
            }
            if (row0 + 8 < N_NODES) {
                g_as1[(row0 + 8) * H1 + head] = sa8;
                g_ad1[(row0 + 8) * H1 + head] = sd8;
            }
        }
    }
}

// ---- layer-1 softmax + aggregation + bias + elu + FUSED layer-2 projection --
// One 128-thread block per node; thread t owns channels [4t, 4t+4), head t/16.
// Single pass over the CSR row (no max subtraction; scores are O(+-10) so
// exp() is safe in fp32 and softmax is shift-invariant). After the weighted
// aggregation + bias + ELU, each thread dots its 4 channels with W2 (smem)
// and a block reduction produces h2[2] and the layer-2 src/dst scores.
__global__ void __launch_bounds__(128) k_agg1(const float* __restrict__ b1,
                                              const float* __restrict__ W2,
                                              const float* __restrict__ asrc2,
                                              const float* __restrict__ adst2) {
    __shared__ float sW2[F1 * 2];
    __shared__ float red0[4], red1[4];
    int n = blockIdx.x;
    int t = threadIdx.x;
    int lane = t & 31, warp = t >> 5;

    #pragma unroll
    for (int i = 0; i < 8; i++) sW2[t + i * 128] = W2[t + i * 128];
    __syncthreads();

    int start = g_off[n], end = g_off[n + 1];
    int ht = t >> 4;
    float adn = g_ad1[n * H1 + ht];

    float den = 0.f;
    float ax = 0.f, ay = 0.f, az = 0.f, aw = 0.f;
    const float4* h4 = (const float4*)g_h1;
    for (int j = start; j < end; j++) {
        int src = g_csr_src[j];
        float e = g_as1[src * H1 + ht] + adn;
        e = (e > 0.f) ? e : NEG_SLOPE * e;
        float w = __expf(e);
        den += w;
        float4 hv = h4[(size_t)src * (F1 / 4) + t];
        ax += w * hv.x; ay += w * hv.y; az += w * hv.z; aw += w * hv.w;
    }
    float inv = 1.f / den;
    float4 bv = ((const float4*)b1)[t];
    float o0 = ax * inv + bv.x;
    float o1 = ay * inv + bv.y;
    float o2 = az * inv + bv.z;
    float o3 = aw * inv + bv.w;
    o0 = (o0 > 0.f) ? o0 : (__expf(o0) - 1.f);
    o1 = (o1 > 0.f) ? o1 : (__expf(o1) - 1.f);
    o2 = (o2 > 0.f) ? o2 : (__expf(o2) - 1.f);
    o3 = (o3 > 0.f) ? o3 : (__expf(o3) - 1.f);

    // fused 512->2 projection
    int c = t * 4;
    float p0 = o0 * sW2[(c + 0) * 2] + o1 * sW2[(c + 1) * 2] +
               o2 * sW2[(c + 2) * 2] + o3 * sW2[(c + 3) * 2];
    float p1 = o0 * sW2[(c + 0) * 2 + 1] + o1 * sW2[(c + 1) * 2 + 1] +
               o2 * sW2[(c + 2) * 2 + 1] + o3 * sW2[(c + 3) * 2 + 1];
    #pragma unroll
    for (int o = 16; o; o >>= 1) {
        p0 += __shfl_xor_sync(0xffffffffu, p0, o);
        p1 += __shfl_xor_sync(0xffffffffu, p1, o);
    }
    if (lane == 0) { red0[warp] = p0; red1[warp] = p1; }
    __syncthreads();
    if (t == 0) {
        float h20 = red0[0] + red0[1] + red0[2] + red0[3];
        float h21 = red1[0] + red1[1] + red1[2] + red1[3];
        g_h2[n * 2 + 0] = h20;
        g_h2[n * 2 + 1] = h21;
        g_as2[n] = h20 * asrc2[0] + h21 * asrc2[1];
        g_ad2[n] = h20 * adst2[0] + h21 * adst2[1];
    }
}

// ---------------- layer-2 softmax + aggregation (warp per node) -------------
__global__ void k_agg2(const float* __restrict__ b2, float* __restrict__ out) {
    int gw = (blockIdx.x * blockDim.x + threadIdx.x) >> 5;
    int lane = threadIdx.x & 31;
    if (gw >= N_NODES) return;
    int start = g_off[gw], end = g_off[gw + 1];
    float adn = g_ad2[gw];

    float den = 0.f, a0 = 0.f, a1 = 0.f;
    for (int j = start + lane; j < end; j += 32) {
        int src = g_csr_src[j];
        float e = g_as2[src] + adn;
        e = (e > 0.f) ? e : NEG_SLOPE * e;
        float w = __expf(e);
        den += w;
        a0 += w * g_h2[src * 2 + 0];
        a1 += w * g_h2[src * 2 + 1];
    }
    #pragma unroll
    for (int off = 16; off; off >>= 1) {
        den += __shfl_xor_sync(0xffffffffu, den, off);
        a0  += __shfl_xor_sync(0xffffffffu, a0, off);
        a1  += __shfl_xor_sync(0xffffffffu, a1, off);
    }
    if (lane == 0) {
        float inv = 1.f / den;
        out[gw * 2 + 0] = a0 * inv + b2[0];
        out[gw * 2 + 1] = a1 * inv + b2[1];
    }
}

// ---------------- launcher ---------------------------------------------------
extern "C" void kernel_launch(void* const* d_in, const int* in_sizes, int n_in,
                              void* d_out, int out_size) {
    const float* x      = (const float*)d_in[0];
    const int*   ei     = (const int*)  d_in[1];
    const float* W1     = (const float*)d_in[2];
    const float* a_src1 = (const float*)d_in[3];
    const float* a_dst1 = (const float*)d_in[4];
    const float* b1     = (const float*)d_in[5];
    const float* W2     = (const float*)d_in[6];
    const float* a_src2 = (const float*)d_in[7];
    const float* a_dst2 = (const float*)d_in[8];
    const float* b2     = (const float*)d_in[9];
    float* out = (float*)d_out;

    static int configured = 0;
    if (!configured) {
        cudaFuncSetAttribute(k_gemm_mma,
                             cudaFuncAttributeMaxDynamicSharedMemorySize,
                             GEMM_SMEM);
        configured = 1;
    }

    // CSR build
    k_init_deg<<<(N_NODES + 255) / 256, 256>>>();
    k_count<<<(N_EDGES + 255) / 256, 256>>>(ei);
    k_scan<<<1, 1024>>>();
    k_scatter<<<(ET + 255) / 256, 256>>>(ei);

    // layer 1: bf16 split + tensor-core GEMM (+fused scores)
    k_prep_a<<<(N_NODES * IN_CH + 255) / 256, 256>>>(x);
    k_prep_b<<<(F1 * IN_CH + 255) / 256, 256>>>(W1);
    dim3 gg((N_NODES + 127) / 128, 4);
    k_gemm_mma<<<gg, 256, GEMM_SMEM>>>(a_src1, a_dst1);

    // layer-1 aggregation fused with layer-2 feature projection
    k_agg1<<<N_NODES, 128>>>(b1, W2, a_src2, a_dst2);

    // layer 2 aggregation -> output
    k_agg2<<<(N_NODES + 7) / 8, 256>>>(b2, out);
}

// round 5
// speedup vs baseline: 1.5571x; 1.1588x over previous
#include <cuda_runtime.h>
#include <cuda_bf16.h>
#include <cuda_fp16.h>
#include <cstdint>

#define N_NODES 50000
#define N_EDGES 800000
#define ET (N_EDGES + N_NODES)   // edges + self loops = 850000
#define IN_CH 128
#define H1 8
#define C1 64
#define F1 (H1 * C1)             // 512
#define NEG_SLOPE 0.2f

// ---------------- scratch (static device globals; no allocation) ------------
__device__ __half g_h1h[N_NODES * F1];    // x @ W1 in fp16   (51.2 MB, L2-resident)
__device__ float g_as1[N_NODES * H1];
__device__ float g_ad1[N_NODES * H1];
__device__ float g_h2[N_NODES * 2];
__device__ float g_as2[N_NODES];
__device__ float g_ad2[N_NODES];
__device__ int   g_deg[N_NODES];
__device__ int   g_off[N_NODES + 1];
__device__ int   g_cur[N_NODES];
__device__ int   g_csr_src[ET];

// bf16 split operands for the tensor-core GEMM
__device__ __nv_bfloat16 g_ah[N_NODES * IN_CH];   // hi(x)     [m][k]
__device__ __nv_bfloat16 g_al[N_NODES * IN_CH];   // lo(x)
__device__ __nv_bfloat16 g_bh[F1 * IN_CH];        // hi(W1^T)  [n][k]
__device__ __nv_bfloat16 g_bl[F1 * IN_CH];        // lo(W1^T)

// ---------------- PTX helpers ------------------------------------------------
__device__ __forceinline__ uint32_t smem_u32(const void* p) {
    uint32_t a;
    asm("{ .reg .u64 t; cvta.to.shared.u64 t, %1; cvt.u32.u64 %0, t; }"
        : "=r"(a) : "l"(p));
    return a;
}

__device__ __forceinline__ void ldm_x4(uint32_t* r, uint32_t addr) {
    asm volatile("ldmatrix.sync.aligned.m8n8.x4.shared.b16 {%0,%1,%2,%3}, [%4];"
                 : "=r"(r[0]), "=r"(r[1]), "=r"(r[2]), "=r"(r[3]) : "r"(addr));
}

__device__ __forceinline__ void mma_bf16(float* d, const uint32_t* a,
                                         const uint32_t* b) {
    asm volatile("mma.sync.aligned.m16n8k16.row.col.f32.bf16.bf16.f32 "
                 "{%0,%1,%2,%3}, {%4,%5,%6,%7}, {%8,%9}, {%0,%1,%2,%3};"
                 : "+f"(d[0]), "+f"(d[1]), "+f"(d[2]), "+f"(d[3])
                 : "r"(a[0]), "r"(a[1]), "r"(a[2]), "r"(a[3]),
                   "r"(b[0]), "r"(b[1]));
}

__device__ __forceinline__ void cp16(uint32_t dst, const void* src,
                                     uint32_t src_bytes) {
    asm volatile("cp.async.cg.shared.global [%0], [%1], 16, %2;"
                 :: "r"(dst), "l"(src), "r"(src_bytes));
}

// ---------------- CSR build -------------------------------------------------
__global__ void k_init_deg() {
    int i = blockIdx.x * blockDim.x + threadIdx.x;
    if (i < N_NODES) g_deg[i] = 1;   // self loop
}

__global__ void k_count(const int* __restrict__ ei) {
    int e = blockIdx.x * blockDim.x + threadIdx.x;
    if (e < N_EDGES) atomicAdd(&g_deg[ei[N_EDGES + e]], 1);
}

__global__ void k_scan() {
    __shared__ int wsum[32];
    int t = threadIdx.x, lane = t & 31, w = t >> 5;
    int carry = 0;
    for (int base = 0; base < N_NODES; base += 1024) {
        int i = base + t;
        int v = (i < N_NODES) ? g_deg[i] : 0;
        int s = v;
        #pragma unroll
        for (int o = 1; o < 32; o <<= 1) {
            int u = __shfl_up_sync(0xffffffffu, s, o);
            if (lane >= o) s += u;
        }
        if (lane == 31) wsum[w] = s;
        __syncthreads();
        if (w == 0) {
            int ws = wsum[lane];
            #pragma unroll
            for (int o = 1; o < 32; o <<= 1) {
                int u = __shfl_up_sync(0xffffffffu, ws, o);
                if (lane >= o) ws += u;
            }
            wsum[lane] = ws;
        }
        __syncthreads();
        int excl = carry + (w ? wsum[w - 1] : 0) + s - v;
        int tot = wsum[31];
        if (i < N_NODES) { g_off[i] = excl; g_cur[i] = excl; }
        carry += tot;
        __syncthreads();
    }
    if (t == 0) g_off[N_NODES] = carry;   // = ET
}

__global__ void k_scatter(const int* __restrict__ ei) {
    int e = blockIdx.x * blockDim.x + threadIdx.x;
    if (e >= ET) return;
    int src, dst;
    if (e < N_EDGES) { src = ei[e]; dst = ei[N_EDGES + e]; }
    else             { src = dst = e - N_EDGES; }
    int pos = atomicAdd(&g_cur[dst], 1);
    g_csr_src[pos] = src;
}

// ---------------- operand prep: bf16 error-free split ------------------------
__global__ void k_prep_a(const float* __restrict__ x) {
    int idx = blockIdx.x * blockDim.x + threadIdx.x;
    if (idx >= N_NODES * IN_CH) return;
    float v = x[idx];
    __nv_bfloat16 hi = __float2bfloat16(v);
    __nv_bfloat16 lo = __float2bfloat16(v - __bfloat162float(hi));
    g_ah[idx] = hi;
    g_al[idx] = lo;
}

__global__ void k_prep_b(const float* __restrict__ W) {
    int idx = blockIdx.x * blockDim.x + threadIdx.x;   // over 512*128
    if (idx >= F1 * IN_CH) return;
    int n = idx & (F1 - 1);
    int k = idx >> 9;
    float v = W[k * F1 + n];                           // coalesced read
    __nv_bfloat16 hi = __float2bfloat16(v);
    __nv_bfloat16 lo = __float2bfloat16(v - __bfloat162float(hi));
    g_bh[n * IN_CH + k] = hi;
    g_bl[n * IN_CH + k] = lo;
}

// ---------------- mma.sync GEMM: h1 = X @ W1  (+ fused attention scores) -----
// Grid (391, 4). CTA tile M=128 x N=128; 8 warps as 4(M) x 2(N), warp tile
// 32x64. K staged in 64-chunks, cp.async double-buffered: 6 stages =
// 3 split terms x 2 k-halves:  term0 Xh*Wh, term1 Xh*Wl, term2 Xl*Wh.
#define AS_STRIDE 72              // halves per row (144B, 16B-aligned)
#define STG_BYTES (128 * AS_STRIDE * 2)          // 18432 per tile buffer
#define GEMM_SMEM (4 * STG_BYTES + 1024)         // A0 A1 B0 B1 + scs

__device__ __forceinline__ void prefetch_stage(int s, int tid, int bm, int nb,
                                               uint32_t sA, uint32_t sB) {
    int term = s >> 1, kof = (s & 1) * 64;
    const __nv_bfloat16* pa = (term == 2) ? g_al : g_ah;
    const __nv_bfloat16* pb = (term == 1) ? g_bl : g_bh;
    #pragma unroll
    for (int it = 0; it < 4; it++) {
        int idx = tid + it * 256;
        int r = idx >> 3, c = idx & 7;
        int grow = bm + r;
        int ok = grow < N_NODES;
        const void* gp = pa + (size_t)(ok ? grow : 0) * IN_CH + kof + c * 8;
        cp16(sA + (uint32_t)(r * AS_STRIDE + c * 8) * 2, gp, ok ? 16u : 0u);
    }
    #pragma unroll
    for (int it = 0; it < 4; it++) {
        int idx = tid + it * 256;
        int r = idx >> 3, c = idx & 7;
        const void* gp = pb + (size_t)(nb * 128 + r) * IN_CH + kof + c * 8;
        cp16(sB + (uint32_t)(r * AS_STRIDE + c * 8) * 2, gp, 16u);
    }
    asm volatile("cp.async.commit_group;" ::: "memory");
}

__global__ void __launch_bounds__(256) k_gemm_mma(
        const float* __restrict__ asrc, const float* __restrict__ adst) {
    extern __shared__ char dyn[];
    uint32_t base = smem_u32(dyn);
    uint32_t sAb[2] = {base, base + STG_BYTES};
    uint32_t sBb[2] = {base + 2 * STG_BYTES, base + 3 * STG_BYTES};
    float* scs = (float*)(dyn + 4 * STG_BYTES);   // [0,128) a_src, [128,256) a_dst

    int tid = threadIdx.x;
    int lane = tid & 31, wid = tid >> 5;
    int wm = wid & 3, wn = wid >> 2;
    int bm = blockIdx.x * 128;
    int nb = blockIdx.y;                 // N block: cols [nb*128, nb*128+128)

    scs[tid] = (tid < 128) ? asrc[nb * 128 + tid] : adst[nb * 128 + tid - 128];

    float acc[2][8][4];
    #pragma unroll
    for (int i = 0; i < 2; i++)
        #pragma unroll
        for (int j = 0; j < 8; j++)
            #pragma unroll
            for (int q = 0; q < 4; q++) acc[i][j][q] = 0.f;

    // ldmatrix lane base offsets (bytes)
    uint32_t a_off0 = (uint32_t)((wm * 32 + (lane & 15)) * AS_STRIDE +
                                 (lane >> 4) * 8) * 2;
    uint32_t b_off0 = (uint32_t)(((lane >> 4) * 8 + (lane & 7)) * AS_STRIDE +
                                 ((lane >> 3) & 1) * 8) * 2;

    prefetch_stage(0, tid, bm, nb, sAb[0], sBb[0]);

    #pragma unroll 1
    for (int s = 0; s < 6; s++) {
        if (s < 5) {
            prefetch_stage(s + 1, tid, bm, nb, sAb[(s + 1) & 1], sBb[(s + 1) & 1]);
            asm volatile("cp.async.wait_group 1;" ::: "memory");
        } else {
            asm volatile("cp.async.wait_group 0;" ::: "memory");
        }
        __syncthreads();

        uint32_t sA = sAb[s & 1], sB = sBb[s & 1];
        #pragma unroll
        for (int ks = 0; ks < 4; ks++) {
            uint32_t af[2][4], bf[4][4];
            #pragma unroll
            for (int mt = 0; mt < 2; mt++)
                ldm_x4(af[mt], sA + a_off0 +
                       (uint32_t)(mt * 16 * AS_STRIDE + ks * 16) * 2);
            #pragma unroll
            for (int np = 0; np < 4; np++)
                ldm_x4(bf[np], sB + b_off0 +
                       (uint32_t)((wn * 64 + np * 16) * AS_STRIDE + ks * 16) * 2);
            #pragma unroll
            for (int mt = 0; mt < 2; mt++)
                #pragma unroll
                for (int np = 0; np < 4; np++) {
                    mma_bf16(acc[mt][np * 2 + 0], af[mt], &bf[np][0]);
                    mma_bf16(acc[mt][np * 2 + 1], af[mt], &bf[np][2]);
                }
        }
        __syncthreads();
    }

    // ---- epilogue: store h1 (fp16) + fused per-head attention scores --------
    int ql = lane & 3, qr = lane >> 2;
    int head = nb * 2 + wn;

    float va[16], vd[16];
    #pragma unroll
    for (int nt = 0; nt < 8; nt++)
        #pragma unroll
        for (int j = 0; j < 2; j++) {
            int cw = wn * 64 + nt * 8 + ql * 2 + j;
            va[nt * 2 + j] = scs[cw];
            vd[nt * 2 + j] = scs[128 + cw];
        }

    #pragma unroll
    for (int mt = 0; mt < 2; mt++) {
        int row0 = bm + wm * 32 + mt * 16 + qr;
        float sa0 = 0.f, sd0 = 0.f, sa8 = 0.f, sd8 = 0.f;
        #pragma unroll
        for (int nt = 0; nt < 8; nt++) {
            float d0 = acc[mt][nt][0], d1 = acc[mt][nt][1];
            float d2 = acc[mt][nt][2], d3 = acc[mt][nt][3];
            sa0 += d0 * va[nt * 2] + d1 * va[nt * 2 + 1];
            sd0 += d0 * vd[nt * 2] + d1 * vd[nt * 2 + 1];
            sa8 += d2 * va[nt * 2] + d3 * va[nt * 2 + 1];
            sd8 += d2 * vd[nt * 2] + d3 * vd[nt * 2 + 1];
            int col = nb * 128 + wn * 64 + nt * 8 + ql * 2;
            if (row0 < N_NODES)
                *(__half2*)(g_h1h + (size_t)row0 * F1 + col) =
                    __floats2half2_rn(d0, d1);
            if (row0 + 8 < N_NODES)
                *(__half2*)(g_h1h + (size_t)(row0 + 8) * F1 + col) =
                    __floats2half2_rn(d2, d3);
        }
        #pragma unroll
        for (int o = 1; o <= 2; o <<= 1) {
            sa0 += __shfl_xor_sync(0xffffffffu, sa0, o);
            sd0 += __shfl_xor_sync(0xffffffffu, sd0, o);
            sa8 += __shfl_xor_sync(0xffffffffu, sa8, o);
            sd8 += __shfl_xor_sync(0xffffffffu, sd8, o);
        }
        if (ql == 0) {
            if (row0 < N_NODES) {
                g_as1[row0 * H1 + head] = sa0;
                g_ad1[row0 * H1 + head] = sd0;
            }
            if (row0 + 8 < N_NODES) {
                g_as1[(row0 + 8) * H1 + head] = sa8;
                g_ad1[(row0 + 8) * H1 + head] = sd8;
            }
        }
    }
}

// ---- layer-1 softmax + aggregation + bias + elu + FUSED layer-2 projection --
// One 128-thread block per node; thread t owns channels [4t, 4t+4), head t/16.
// Single pass over the CSR row (scores are O(+-10): exp without max-shift is
// safe in fp32; softmax is shift-invariant). Features gathered in fp16
// (L2-resident table), accumulated in fp32.
__global__ void __launch_bounds__(128) k_agg1(const float* __restrict__ b1,
                                              const float* __restrict__ W2,
                                              const float* __restrict__ asrc2,
                                              const float* __restrict__ adst2) {
    __shared__ float sW2[F1 * 2];
    __shared__ float red0[4], red1[4];
    int n = blockIdx.x;
    int t = threadIdx.x;
    int lane = t & 31, warp = t >> 5;

    #pragma unroll
    for (int i = 0; i < 8; i++) sW2[t + i * 128] = W2[t + i * 128];
    __syncthreads();

    int start = g_off[n], end = g_off[n + 1];
    int ht = t >> 4;
    float adn = g_ad1[n * H1 + ht];

    float den = 0.f;
    float ax = 0.f, ay = 0.f, az = 0.f, aw = 0.f;
    const uint2* h4 = (const uint2*)g_h1h;   // 4 halves per uint2
    #pragma unroll 2
    for (int j = start; j < end; j++) {
        int src = g_csr_src[j];
        float e = g_as1[src * H1 + ht] + adn;
        e = (e > 0.f) ? e : NEG_SLOPE * e;
        float w = __expf(e);
        den += w;
        uint2 hv = h4[(size_t)src * (F1 / 4) + t];
        float2 f01 = __half22float2(*(__half2*)&hv.x);
        float2 f23 = __half22float2(*(__half2*)&hv.y);
        ax += w * f01.x; ay += w * f01.y; az += w * f23.x; aw += w * f23.y;
    }
    float inv = 1.f / den;
    float4 bv = ((const float4*)b1)[t];
    float o0 = ax * inv + bv.x;
    float o1 = ay * inv + bv.y;
    float o2 = az * inv + bv.z;
    float o3 = aw * inv + bv.w;
    o0 = (o0 > 0.f) ? o0 : (__expf(o0) - 1.f);
    o1 = (o1 > 0.f) ? o1 : (__expf(o1) - 1.f);
    o2 = (o2 > 0.f) ? o2 : (__expf(o2) - 1.f);
    o3 = (o3 > 0.f) ? o3 : (__expf(o3) - 1.f);

    // fused 512->2 projection
    int c = t * 4;
    float p0 = o0 * sW2[(c + 0) * 2] + o1 * sW2[(c + 1) * 2] +
               o2 * sW2[(c + 2) * 2] + o3 * sW2[(c + 3) * 2];
    float p1 = o0 * sW2[(c + 0) * 2 + 1] + o1 * sW2[(c + 1) * 2 + 1] +
               o2 * sW2[(c + 2) * 2 + 1] + o3 * sW2[(c + 3) * 2 + 1];
    #pragma unroll
    for (int o = 16; o; o >>= 1) {
        p0 += __shfl_xor_sync(0xffffffffu, p0, o);
        p1 += __shfl_xor_sync(0xffffffffu, p1, o);
    }
    if (lane == 0) { red0[warp] = p0; red1[warp] = p1; }
    __syncthreads();
    if (t == 0) {
        float h20 = red0[0] + red0[1] + red0[2] + red0[3];
        float h21 = red1[0] + red1[1] + red1[2] + red1[3];
        g_h2[n * 2 + 0] = h20;
        g_h2[n * 2 + 1] = h21;
        g_as2[n] = h20 * asrc2[0] + h21 * asrc2[1];
        g_ad2[n] = h20 * adst2[0] + h21 * adst2[1];
    }
}

// ---------------- layer-2 softmax + aggregation (warp per node) -------------
__global__ void k_agg2(const float* __restrict__ b2, float* __restrict__ out) {
    int gw = (blockIdx.x * blockDim.x + threadIdx.x) >> 5;
    int lane = threadIdx.x & 31;
    if (gw >= N_NODES) return;
    int start = g_off[gw], end = g_off[gw + 1];
    float adn = g_ad2[gw];

    float den = 0.f, a0 = 0.f, a1 = 0.f;
    for (int j = start + lane; j < end; j += 32) {
        int src = g_csr_src[j];
        float e = g_as2[src] + adn;
        e = (e > 0.f) ? e : NEG_SLOPE * e;
        float w = __expf(e);
        den += w;
        a0 += w * g_h2[src * 2 + 0];
        a1 += w * g_h2[src * 2 + 1];
    }
    #pragma unroll
    for (int off = 16; off; off >>= 1) {
        den += __shfl_xor_sync(0xffffffffu, den, off);
        a0  += __shfl_xor_sync(0xffffffffu, a0, off);
        a1  += __shfl_xor_sync(0xffffffffu, a1, off);
    }
    if (lane == 0) {
        float inv = 1.f / den;
        out[gw * 2 + 0] = a0 * inv + b2[0];
        out[gw * 2 + 1] = a1 * inv + b2[1];
    }
}

// ---------------- launcher ---------------------------------------------------
extern "C" void kernel_launch(void* const* d_in, const int* in_sizes, int n_in,
                              void* d_out, int out_size) {
    const float* x      = (const float*)d_in[0];
    const int*   ei     = (const int*)  d_in[1];
    const float* W1     = (const float*)d_in[2];
    const float* a_src1 = (const float*)d_in[3];
    const float* a_dst1 = (const float*)d_in[4];
    const float* b1     = (const float*)d_in[5];
    const float* W2     = (const float*)d_in[6];
    const float* a_src2 = (const float*)d_in[7];
    const float* a_dst2 = (const float*)d_in[8];
    const float* b2     = (const float*)d_in[9];
    float* out = (float*)d_out;

    static int configured = 0;
    if (!configured) {
        cudaFuncSetAttribute(k_gemm_mma,
                             cudaFuncAttributeMaxDynamicSharedMemorySize,
                             GEMM_SMEM);
        configured = 1;
    }

    // CSR build
    k_init_deg<<<(N_NODES + 255) / 256, 256>>>();
    k_count<<<(N_EDGES + 255) / 256, 256>>>(ei);
    k_scan<<<1, 1024>>>();
    k_scatter<<<(ET + 255) / 256, 256>>>(ei);

    // layer 1: bf16 split + tensor-core GEMM (+fused scores)
    k_prep_a<<<(N_NODES * IN_CH + 255) / 256, 256>>>(x);
    k_prep_b<<<(F1 * IN_CH + 255) / 256, 256>>>(W1);
    dim3 gg((N_NODES + 127) / 128, 4);
    k_gemm_mma<<<gg, 256, GEMM_SMEM>>>(a_src1, a_dst1);

    // layer-1 aggregation fused with layer-2 feature projection
    k_agg1<<<N_NODES, 128>>>(b1, W2, a_src2, a_dst2);

    // layer 2 aggregation -> output
    k_agg2<<<(N_NODES + 7) / 8, 256>>>(b2, out);
}

// round 6
// speedup vs baseline: 1.6770x; 1.0770x over previous
#include <cuda_runtime.h>
#include <cuda_bf16.h>
#include <cuda_fp16.h>
#include <cstdint>

#define N_NODES 50000
#define N_EDGES 800000
#define ET (N_EDGES + N_NODES)   // edges + self loops = 850000
#define IN_CH 128
#define H1 8
#define C1 64
#define F1 (H1 * C1)             // 512
#define NEG_SLOPE 0.2f

// ---------------- scratch (static device globals; no allocation) ------------
__device__ __half g_h1h[N_NODES * F1];    // x @ W1 in fp16   (51.2 MB, L2-resident)
__device__ float g_as1[N_NODES * H1];
__device__ float g_ad1[N_NODES * H1];
__device__ float g_h2[N_NODES * 2];
__device__ float g_as2[N_NODES];
__device__ float g_ad2[N_NODES];
__device__ int   g_deg[N_NODES];
__device__ int   g_off[N_NODES + 1];
__device__ int   g_cur[N_NODES];
__device__ int   g_csr_src[ET];

// fp16 split operands for the tensor-core GEMM:  x = Xh + Xl (error-free),
// W rounded once to fp16.  D = (Xh + Xl) @ Wh  -> only W-rounding error.
__device__ __half g_ah[N_NODES * IN_CH];   // hi(x)     [m][k]
__device__ __half g_al[N_NODES * IN_CH];   // lo(x)
__device__ __half g_bh[F1 * IN_CH];        // fp16(W1^T) [n][k]

// ---------------- PTX helpers ------------------------------------------------
__device__ __forceinline__ uint32_t smem_u32(const void* p) {
    uint32_t a;
    asm("{ .reg .u64 t; cvta.to.shared.u64 t, %1; cvt.u32.u64 %0, t; }"
        : "=r"(a) : "l"(p));
    return a;
}

__device__ __forceinline__ void ldm_x4(uint32_t* r, uint32_t addr) {
    asm volatile("ldmatrix.sync.aligned.m8n8.x4.shared.b16 {%0,%1,%2,%3}, [%4];"
                 : "=r"(r[0]), "=r"(r[1]), "=r"(r[2]), "=r"(r[3]) : "r"(addr));
}

__device__ __forceinline__ void mma_fp16(float* d, const uint32_t* a,
                                         const uint32_t* b) {
    asm volatile("mma.sync.aligned.m16n8k16.row.col.f32.f16.f16.f32 "
                 "{%0,%1,%2,%3}, {%4,%5,%6,%7}, {%8,%9}, {%0,%1,%2,%3};"
                 : "+f"(d[0]), "+f"(d[1]), "+f"(d[2]), "+f"(d[3])
                 : "r"(a[0]), "r"(a[1]), "r"(a[2]), "r"(a[3]),
                   "r"(b[0]), "r"(b[1]));
}

__device__ __forceinline__ void cp16(uint32_t dst, const void* src,
                                     uint32_t src_bytes) {
    asm volatile("cp.async.cg.shared.global [%0], [%1], 16, %2;"
                 :: "r"(dst), "l"(src), "r"(src_bytes));
}

// ---------------- CSR build -------------------------------------------------
__global__ void k_init_deg() {
    int i = blockIdx.x * blockDim.x + threadIdx.x;
    if (i < N_NODES) g_deg[i] = 1;   // self loop
}

__global__ void k_count(const int* __restrict__ ei) {
    int e = blockIdx.x * blockDim.x + threadIdx.x;
    if (e < N_EDGES) atomicAdd(&g_deg[ei[N_EDGES + e]], 1);
}

__global__ void k_scan() {
    __shared__ int wsum[32];
    int t = threadIdx.x, lane = t & 31, w = t >> 5;
    int carry = 0;
    for (int base = 0; base < N_NODES; base += 1024) {
        int i = base + t;
        int v = (i < N_NODES) ? g_deg[i] : 0;
        int s = v;
        #pragma unroll
        for (int o = 1; o < 32; o <<= 1) {
            int u = __shfl_up_sync(0xffffffffu, s, o);
            if (lane >= o) s += u;
        }
        if (lane == 31) wsum[w] = s;
        __syncthreads();
        if (w == 0) {
            int ws = wsum[lane];
            #pragma unroll
            for (int o = 1; o < 32; o <<= 1) {
                int u = __shfl_up_sync(0xffffffffu, ws, o);
                if (lane >= o) ws += u;
            }
            wsum[lane] = ws;
        }
        __syncthreads();
        int excl = carry + (w ? wsum[w - 1] : 0) + s - v;
        int tot = wsum[31];
        if (i < N_NODES) { g_off[i] = excl; g_cur[i] = excl; }
        carry += tot;
        __syncthreads();
    }
    if (t == 0) g_off[N_NODES] = carry;   // = ET
}

__global__ void k_scatter(const int* __restrict__ ei) {
    int e = blockIdx.x * blockDim.x + threadIdx.x;
    if (e >= ET) return;
    int src, dst;
    if (e < N_EDGES) { src = ei[e]; dst = ei[N_EDGES + e]; }
    else             { src = dst = e - N_EDGES; }
    int pos = atomicAdd(&g_cur[dst], 1);
    g_csr_src[pos] = src;
}

// ---------------- operand prep: fp16 error-free split of X -------------------
__global__ void k_prep_a(const float* __restrict__ x) {
    int idx = blockIdx.x * blockDim.x + threadIdx.x;
    if (idx >= N_NODES * IN_CH) return;
    float v = x[idx];
    __half hi = __float2half_rn(v);
    __half lo = __float2half_rn(v - __half2float(hi));
    g_ah[idx] = hi;
    g_al[idx] = lo;
}

__global__ void k_prep_b(const float* __restrict__ W) {
    int idx = blockIdx.x * blockDim.x + threadIdx.x;   // over 512*128
    if (idx >= F1 * IN_CH) return;
    int n = idx & (F1 - 1);
    int k = idx >> 9;
    g_bh[n * IN_CH + k] = __float2half_rn(W[k * F1 + n]);  // coalesced read
}

// ---------------- mma.sync GEMM: h1 = X @ W1  (+ fused attention scores) -----
// Grid (391, 4). CTA tile M=128 x N=128; 8 warps as 4(M) x 2(N), warp tile
// 32x64. K staged in 64-chunks, cp.async double-buffered: 4 stages =
// 2 split terms (Xh, Xl) x 2 k-halves, B = fp16(W) for all stages.
#define AS_STRIDE 72              // halves per row (144B, 16B-aligned)
#define STG_BYTES (128 * AS_STRIDE * 2)          // 18432 per tile buffer
#define GEMM_SMEM (4 * STG_BYTES + 1024)         // A0 A1 B0 B1 + scs

__device__ __forceinline__ void prefetch_stage(int s, int tid, int bm, int nb,
                                               uint32_t sA, uint32_t sB) {
    int term = s >> 1, kof = (s & 1) * 64;
    const __half* pa = term ? g_al : g_ah;
    const __half* pb = g_bh;
    #pragma unroll
    for (int it = 0; it < 4; it++) {
        int idx = tid + it * 256;
        int r = idx >> 3, c = idx & 7;
        int grow = bm + r;
        int ok = grow < N_NODES;
        const void* gp = pa + (size_t)(ok ? grow : 0) * IN_CH + kof + c * 8;
        cp16(sA + (uint32_t)(r * AS_STRIDE + c * 8) * 2, gp, ok ? 16u : 0u);
    }
    if (s < 2) {   // B tiles identical for both terms: load only for s=0,1
        #pragma unroll
        for (int it = 0; it < 4; it++) {
            int idx = tid + it * 256;
            int r = idx >> 3, c = idx & 7;
            const void* gp = pb + (size_t)(nb * 128 + r) * IN_CH + kof + c * 8;
            cp16(sB + (uint32_t)(r * AS_STRIDE + c * 8) * 2, gp, 16u);
        }
    }
    asm volatile("cp.async.commit_group;" ::: "memory");
}

__global__ void __launch_bounds__(256) k_gemm_mma(
        const float* __restrict__ asrc, const float* __restrict__ adst) {
    extern __shared__ char dyn[];
    uint32_t base = smem_u32(dyn);
    uint32_t sAb[2] = {base, base + STG_BYTES};
    uint32_t sBb[2] = {base + 2 * STG_BYTES, base + 3 * STG_BYTES};
    float* scs = (float*)(dyn + 4 * STG_BYTES);   // [0,128) a_src, [128,256) a_dst

    int tid = threadIdx.x;
    int lane = tid & 31, wid = tid >> 5;
    int wm = wid & 3, wn = wid >> 2;
    int bm = blockIdx.x * 128;
    int nb = blockIdx.y;                 // N block: cols [nb*128, nb*128+128)

    scs[tid] = (tid < 128) ? asrc[nb * 128 + tid] : adst[nb * 128 + tid - 128];

    float acc[2][8][4];
    #pragma unroll
    for (int i = 0; i < 2; i++)
        #pragma unroll
        for (int j = 0; j < 8; j++)
            #pragma unroll
            for (int q = 0; q < 4; q++) acc[i][j][q] = 0.f;

    // ldmatrix lane base offsets (bytes)
    uint32_t a_off0 = (uint32_t)((wm * 32 + (lane & 15)) * AS_STRIDE +
                                 (lane >> 4) * 8) * 2;
    uint32_t b_off0 = (uint32_t)(((lane >> 4) * 8 + (lane & 7)) * AS_STRIDE +
                                 ((lane >> 3) & 1) * 8) * 2;

    prefetch_stage(0, tid, bm, nb, sAb[0], sBb[0]);

    // stages: 0:(Xh,k0) 1:(Xh,k1) 2:(Xl,k0) 3:(Xl,k1); B buffers reused (s&1).
    #pragma unroll 1
    for (int s = 0; s < 4; s++) {
        if (s < 3) {
            prefetch_stage(s + 1, tid, bm, nb, sAb[(s + 1) & 1], sBb[(s + 1) & 1]);
            asm volatile("cp.async.wait_group 1;" ::: "memory");
        } else {
            asm volatile("cp.async.wait_group 0;" ::: "memory");
        }
        __syncthreads();

        uint32_t sA = sAb[s & 1], sB = sBb[s & 1];
        #pragma unroll
        for (int ks = 0; ks < 4; ks++) {
            uint32_t af[2][4], bf[4][4];
            #pragma unroll
            for (int mt = 0; mt < 2; mt++)
                ldm_x4(af[mt], sA + a_off0 +
                       (uint32_t)(mt * 16 * AS_STRIDE + ks * 16) * 2);
            #pragma unroll
            for (int np = 0; np < 4; np++)
                ldm_x4(bf[np], sB + b_off0 +
                       (uint32_t)((wn * 64 + np * 16) * AS_STRIDE + ks * 16) * 2);
            #pragma unroll
            for (int mt = 0; mt < 2; mt++)
                #pragma unroll
                for (int np = 0; np < 4; np++) {
                    mma_fp16(acc[mt][np * 2 + 0], af[mt], &bf[np][0]);
                    mma_fp16(acc[mt][np * 2 + 1], af[mt], &bf[np][2]);
                }
        }
        __syncthreads();
    }

    // ---- epilogue: store h1 (fp16) + fused per-head attention scores --------
    int ql = lane & 3, qr = lane >> 2;
    int head = nb * 2 + wn;

    float va[16], vd[16];
    #pragma unroll
    for (int nt = 0; nt < 8; nt++)
        #pragma unroll
        for (int j = 0; j < 2; j++) {
            int cw = wn * 64 + nt * 8 + ql * 2 + j;
            va[nt * 2 + j] = scs[cw];
            vd[nt * 2 + j] = scs[128 + cw];
        }

    #pragma unroll
    for (int mt = 0; mt < 2; mt++) {
        int row0 = bm + wm * 32 + mt * 16 + qr;
        float sa0 = 0.f, sd0 = 0.f, sa8 = 0.f, sd8 = 0.f;
        #pragma unroll
        for (int nt = 0; nt < 8; nt++) {
            float d0 = acc[mt][nt][0], d1 = acc[mt][nt][1];
            float d2 = acc[mt][nt][2], d3 = acc[mt][nt][3];
            sa0 += d0 * va[nt * 2] + d1 * va[nt * 2 + 1];
            sd0 += d0 * vd[nt * 2] + d1 * vd[nt * 2 + 1];
            sa8 += d2 * va[nt * 2] + d3 * va[nt * 2 + 1];
            sd8 += d2 * vd[nt * 2] + d3 * vd[nt * 2 + 1];
            int col = nb * 128 + wn * 64 + nt * 8 + ql * 2;
            if (row0 < N_NODES)
                *(__half2*)(g_h1h + (size_t)row0 * F1 + col) =
                    __floats2half2_rn(d0, d1);
            if (row0 + 8 < N_NODES)
                *(__half2*)(g_h1h + (size_t)(row0 + 8) * F1 + col) =
                    __floats2half2_rn(d2, d3);
        }
        #pragma unroll
        for (int o = 1; o <= 2; o <<= 1) {
            sa0 += __shfl_xor_sync(0xffffffffu, sa0, o);
            sd0 += __shfl_xor_sync(0xffffffffu, sd0, o);
            sa8 += __shfl_xor_sync(0xffffffffu, sa8, o);
            sd8 += __shfl_xor_sync(0xffffffffu, sd8, o);
        }
        if (ql == 0) {
            if (row0 < N_NODES) {
                g_as1[row0 * H1 + head] = sa0;
                g_ad1[row0 * H1 + head] = sd0;
            }
            if (row0 + 8 < N_NODES) {
                g_as1[(row0 + 8) * H1 + head] = sa8;
                g_ad1[(row0 + 8) * H1 + head] = sd8;
            }
        }
    }
}

// ---- layer-1 softmax + aggregation + bias + elu + FUSED layer-2 projection --
// One 128-thread block per node. Two-phase per 128-edge chunk:
//   phase 1: thread-per-edge computes the 8 per-head weights (8 exps/edge,
//            not 128) into smem, plus src index.
//   phase 2: all threads stream features with addresses known from smem —
//            independent loads, high MLP. Thread t owns channels [4t,4t+4).
__global__ void __launch_bounds__(128) k_agg1(const float* __restrict__ b1,
                                              const float* __restrict__ W2,
                                              const float* __restrict__ asrc2,
                                              const float* __restrict__ adst2) {
    __shared__ float sW2[F1 * 2];
    __shared__ int   ssrc[128];
    __shared__ float sw[128 * 8];
    __shared__ float sadn[8];
    __shared__ float red0[4], red1[4];

    int n = blockIdx.x;
    int t = threadIdx.x;
    int lane = t & 31, warp = t >> 5;

    #pragma unroll
    for (int i = 0; i < 8; i++) sW2[t + i * 128] = W2[t + i * 128];
    if (t < 8) sadn[t] = g_ad1[n * H1 + t];

    int start = g_off[n], end = g_off[n + 1];
    int deg = end - start;
    int ht = t >> 4;

    float den = 0.f;
    float ax = 0.f, ay = 0.f, az = 0.f, aw = 0.f;
    const uint2* h4 = (const uint2*)g_h1h;   // 4 halves per uint2

    for (int c0 = 0; c0 < deg; c0 += 128) {
        int clen = min(128, deg - c0);
        __syncthreads();
        if (t < clen) {
            int src = g_csr_src[start + c0 + t];
            ssrc[t] = src;
            float4 s01 = *(const float4*)(g_as1 + src * H1);
            float4 s45 = *(const float4*)(g_as1 + src * H1 + 4);
            float es[8] = {s01.x, s01.y, s01.z, s01.w,
                           s45.x, s45.y, s45.z, s45.w};
            #pragma unroll
            for (int h = 0; h < 8; h++) {
                float e = es[h] + sadn[h];
                e = (e > 0.f) ? e : NEG_SLOPE * e;
                sw[t * 8 + h] = __expf(e);
            }
        }
        __syncthreads();

        int jj = 0;
        for (; jj + 4 <= clen; jj += 4) {
            int s0 = ssrc[jj], s1 = ssrc[jj + 1], s2 = ssrc[jj + 2],
                s3 = ssrc[jj + 3];
            float w0 = sw[(jj + 0) * 8 + ht];
            float w1 = sw[(jj + 1) * 8 + ht];
            float w2 = sw[(jj + 2) * 8 + ht];
            float w3 = sw[(jj + 3) * 8 + ht];
            uint2 v0 = h4[(size_t)s0 * (F1 / 4) + t];
            uint2 v1 = h4[(size_t)s1 * (F1 / 4) + t];
            uint2 v2 = h4[(size_t)s2 * (F1 / 4) + t];
            uint2 v3 = h4[(size_t)s3 * (F1 / 4) + t];
            den += (w0 + w1) + (w2 + w3);
            float2 a0 = __half22float2(*(__half2*)&v0.x);
            float2 b0 = __half22float2(*(__half2*)&v0.y);
            ax += w0 * a0.x; ay += w0 * a0.y; az += w0 * b0.x; aw += w0 * b0.y;
            float2 a1 = __half22float2(*(__half2*)&v1.x);
            float2 b1v = __half22float2(*(__half2*)&v1.y);
            ax += w1 * a1.x; ay += w1 * a1.y; az += w1 * b1v.x; aw += w1 * b1v.y;
            float2 a2 = __half22float2(*(__half2*)&v2.x);
            float2 b2v = __half22float2(*(__half2*)&v2.y);
            ax += w2 * a2.x; ay += w2 * a2.y; az += w2 * b2v.x; aw += w2 * b2v.y;
            float2 a3 = __half22float2(*(__half2*)&v3.x);
            float2 b3v = __half22float2(*(__half2*)&v3.y);
            ax += w3 * a3.x; ay += w3 * a3.y; az += w3 * b3v.x; aw += w3 * b3v.y;
        }
        for (; jj < clen; jj++) {
            int src = ssrc[jj];
            float w = sw[jj * 8 + ht];
            den += w;
            uint2 hv = h4[(size_t)src * (F1 / 4) + t];
            float2 f01 = __half22float2(*(__half2*)&hv.x);
            float2 f23 = __half22float2(*(__half2*)&hv.y);
            ax += w * f01.x; ay += w * f01.y; az += w * f23.x; aw += w * f23.y;
        }
    }

    float inv = 1.f / den;
    float4 bv = ((const float4*)b1)[t];
    float o0 = ax * inv + bv.x;
    float o1 = ay * inv + bv.y;
    float o2 = az * inv + bv.z;
    float o3 = aw * inv + bv.w;
    o0 = (o0 > 0.f) ? o0 : (__expf(o0) - 1.f);
    o1 = (o1 > 0.f) ? o1 : (__expf(o1) - 1.f);
    o2 = (o2 > 0.f) ? o2 : (__expf(o2) - 1.f);
    o3 = (o3 > 0.f) ? o3 : (__expf(o3) - 1.f);

    // fused 512->2 projection
    int c = t * 4;
    float p0 = o0 * sW2[(c + 0) * 2] + o1 * sW2[(c + 1) * 2] +
               o2 * sW2[(c + 2) * 2] + o3 * sW2[(c + 3) * 2];
    float p1 = o0 * sW2[(c + 0) * 2 + 1] + o1 * sW2[(c + 1) * 2 + 1] +
               o2 * sW2[(c + 2) * 2 + 1] + o3 * sW2[(c + 3) * 2 + 1];
    #pragma unroll
    for (int o = 16; o; o >>= 1) {
        p0 += __shfl_xor_sync(0xffffffffu, p0, o);
        p1 += __shfl_xor_sync(0xffffffffu, p1, o);
    }
    if (lane == 0) { red0[warp] = p0; red1[warp] = p1; }
    __syncthreads();
    if (t == 0) {
        float h20 = red0[0] + red0[1] + red0[2] + red0[3];
        float h21 = red1[0] + red1[1] + red1[2] + red1[3];
        g_h2[n * 2 + 0] = h20;
        g_h2[n * 2 + 1] = h21;
        g_as2[n] = h20 * asrc2[0] + h21 * asrc2[1];
        g_ad2[n] = h20 * adst2[0] + h21 * adst2[1];
    }
}

// ---------------- layer-2 softmax + aggregation (warp per node) -------------
__global__ void k_agg2(const float* __restrict__ b2, float* __restrict__ out) {
    int gw = (blockIdx.x * blockDim.x + threadIdx.x) >> 5;
    int lane = threadIdx.x & 31;
    if (gw >= N_NODES) return;
    int start = g_off[gw], end = g_off[gw + 1];
    float adn = g_ad2[gw];

    float den = 0.f, a0 = 0.f, a1 = 0.f;
    for (int j = start + lane; j < end; j += 32) {
        int src = g_csr_src[j];
        float e = g_as2[src] + adn;
        e = (e > 0.f) ? e : NEG_SLOPE * e;
        float w = __expf(e);
        den += w;
        a0 += w * g_h2[src * 2 + 0];
        a1 += w * g_h2[src * 2 + 1];
    }
    #pragma unroll
    for (int off = 16; off; off >>= 1) {
        den += __shfl_xor_sync(0xffffffffu, den, off);
        a0  += __shfl_xor_sync(0xffffffffu, a0, off);
        a1  += __shfl_xor_sync(0xffffffffu, a1, off);
    }
    if (lane == 0) {
        float inv = 1.f / den;
        out[gw * 2 + 0] = a0 * inv + b2[0];
        out[gw * 2 + 1] = a1 * inv + b2[1];
    }
}

// ---------------- launcher ---------------------------------------------------
extern "C" void kernel_launch(void* const* d_in, const int* in_sizes, int n_in,
                              void* d_out, int out_size) {
    const float* x      = (const float*)d_in[0];
    const int*   ei     = (const int*)  d_in[1];
    const float* W1     = (const float*)d_in[2];
    const float* a_src1 = (const float*)d_in[3];
    const float* a_dst1 = (const float*)d_in[4];
    const float* b1     = (const float*)d_in[5];
    const float* W2     = (const float*)d_in[6];
    const float* a_src2 = (const float*)d_in[7];
    const float* a_dst2 = (const float*)d_in[8];
    const float* b2     = (const float*)d_in[9];
    float* out = (float*)d_out;

    static int configured = 0;
    if (!configured) {
        cudaFuncSetAttribute(k_gemm_mma,
                             cudaFuncAttributeMaxDynamicSharedMemorySize,
                             GEMM_SMEM);
        configured = 1;
    }

    // GEMM path first (independent of CSR; also places k_gemm_mma in the
    // ncu capture slot).
    k_prep_a<<<(N_NODES * IN_CH + 255) / 256, 256>>>(x);
    k_prep_b<<<(F1 * IN_CH + 255) / 256, 256>>>(W1);
    k_init_deg<<<(N_NODES + 255) / 256, 256>>>();
    dim3 gg((N_NODES + 127) / 128, 4);
    k_gemm_mma<<<gg, 256, GEMM_SMEM>>>(a_src1, a_dst1);

    // CSR build
    k_count<<<(N_EDGES + 255) / 256, 256>>>(ei);
    k_scan<<<1, 1024>>>();
    k_scatter<<<(ET + 255) / 256, 256>>>(ei);

    // layer-1 aggregation fused with layer-2 feature projection
    k_agg1<<<N_NODES, 128>>>(b1, W2, a_src2, a_dst2);

    // layer 2 aggregation -> output
    k_agg2<<<(N_NODES + 7) / 8, 256>>>(b2, out);
}

// round 7
// speedup vs baseline: 1.8216x; 1.0862x over previous
#include <cuda_runtime.h>
#include <cuda_fp16.h>
#include <cstdint>

#define N_NODES 50000
#define N_EDGES 800000
#define ET (N_EDGES + N_NODES)   // edges + self loops = 850000
#define IN_CH 128
#define H1 8
#define C1 64
#define F1 (H1 * C1)             // 512
#define NEG_SLOPE 0.2f

// ---------------- scratch (static device globals; no allocation) ------------
__device__ __half g_h1h[N_NODES * F1];    // x @ W1 in fp16   (51.2 MB, L2-resident)
__device__ float g_as1[N_NODES * H1];
__device__ float g_ad1[N_NODES * H1];
__device__ float g_h2[N_NODES * 2];
__device__ float g_as2[N_NODES];
__device__ float g_ad2[N_NODES];
__device__ int   g_deg[N_NODES];
__device__ int   g_off[N_NODES + 1];
__device__ int   g_cur[N_NODES];
__device__ int   g_csr_src[ET];

__device__ __half g_ah[N_NODES * IN_CH];   // fp16(x)    [m][k]
__device__ __half g_bh[F1 * IN_CH];        // fp16(W1^T) [n][k]

// ---------------- PTX helpers ------------------------------------------------
__device__ __forceinline__ uint32_t smem_u32(const void* p) {
    uint32_t a;
    asm("{ .reg .u64 t; cvta.to.shared.u64 t, %1; cvt.u32.u64 %0, t; }"
        : "=r"(a) : "l"(p));
    return a;
}

__device__ __forceinline__ void ldm_x4(uint32_t* r, uint32_t addr) {
    asm volatile("ldmatrix.sync.aligned.m8n8.x4.shared.b16 {%0,%1,%2,%3}, [%4];"
                 : "=r"(r[0]), "=r"(r[1]), "=r"(r[2]), "=r"(r[3]) : "r"(addr));
}

__device__ __forceinline__ void mma_fp16(float* d, const uint32_t* a,
                                         const uint32_t* b) {
    asm volatile("mma.sync.aligned.m16n8k16.row.col.f32.f16.f16.f32 "
                 "{%0,%1,%2,%3}, {%4,%5,%6,%7}, {%8,%9}, {%0,%1,%2,%3};"
                 : "+f"(d[0]), "+f"(d[1]), "+f"(d[2]), "+f"(d[3])
                 : "r"(a[0]), "r"(a[1]), "r"(a[2]), "r"(a[3]),
                   "r"(b[0]), "r"(b[1]));
}

__device__ __forceinline__ void cp16(uint32_t dst, const void* src,
                                     uint32_t src_bytes) {
    asm volatile("cp.async.cg.shared.global [%0], [%1], 16, %2;"
                 :: "r"(dst), "l"(src), "r"(src_bytes));
}

// ---------------- CSR build -------------------------------------------------
__global__ void k_count(const int* __restrict__ ei) {
    int e = blockIdx.x * blockDim.x + threadIdx.x;
    if (e < N_EDGES) atomicAdd(&g_deg[ei[N_EDGES + e]], 1);
}

// 1024 threads, 4 nodes/thread/iter. Adds +1 per node (self loop), zeroes
// g_deg for the next graph replay, writes exclusive offsets to g_off/g_cur.
__global__ void k_scan() {
    __shared__ int wsum[2][32];
    int t = threadIdx.x, lane = t & 31, w = t >> 5;
    int carry = 0;
    int p = 0;
    for (int base = 0; base < N_NODES; base += 4096, p ^= 1) {
        int i = base + t * 4;
        int c0 = 0, c1 = 0, c2 = 0, c3 = 0;
        if (i + 3 < N_NODES) {
            int4 v = *(int4*)&g_deg[i];
            *(int4*)&g_deg[i] = make_int4(0, 0, 0, 0);
            c0 = v.x + 1; c1 = v.y + 1; c2 = v.z + 1; c3 = v.w + 1;
        } else if (i < N_NODES) {
            int cc[4] = {0, 0, 0, 0};
            for (int q = 0; q < 4; q++)
                if (i + q < N_NODES) { cc[q] = g_deg[i + q] + 1; g_deg[i + q] = 0; }
            c0 = cc[0]; c1 = cc[1]; c2 = cc[2]; c3 = cc[3];
        }
        int tsum = c0 + c1 + c2 + c3;
        int s = tsum;
        #pragma unroll
        for (int o = 1; o < 32; o <<= 1) {
            int u = __shfl_up_sync(0xffffffffu, s, o);
            if (lane >= o) s += u;
        }
        if (lane == 31) wsum[p][w] = s;
        __syncthreads();
        if (w == 0) {
            int ws = wsum[p][lane];
            #pragma unroll
            for (int o = 1; o < 32; o <<= 1) {
                int u = __shfl_up_sync(0xffffffffu, ws, o);
                if (lane >= o) ws += u;
            }
            wsum[p][lane] = ws;
        }
        __syncthreads();
        int excl = carry + (w ? wsum[p][w - 1] : 0) + s - tsum;
        int o0 = excl, o1 = o0 + c0, o2 = o1 + c1, o3 = o2 + c2;
        if (i + 3 < N_NODES) {
            *(int4*)&g_off[i] = make_int4(o0, o1, o2, o3);
            *(int4*)&g_cur[i] = make_int4(o0, o1, o2, o3);
        } else {
            int oo[4] = {o0, o1, o2, o3};
            for (int q = 0; q < 4; q++)
                if (i + q < N_NODES) { g_off[i + q] = oo[q]; g_cur[i + q] = oo[q]; }
        }
        carry += wsum[p][31];
    }
    if (t == 0) g_off[N_NODES] = carry;   // = ET
}

__global__ void k_scatter(const int* __restrict__ ei) {
    int e = blockIdx.x * blockDim.x + threadIdx.x;
    if (e >= ET) return;
    int src, dst;
    if (e < N_EDGES) { src = ei[e]; dst = ei[N_EDGES + e]; }
    else             { src = dst = e - N_EDGES; }
    int pos = atomicAdd(&g_cur[dst], 1);
    g_csr_src[pos] = src;
}

// ---------------- operand prep ------------------------------------------------
__global__ void k_prep_a(const float* __restrict__ x) {
    int idx = blockIdx.x * blockDim.x + threadIdx.x;   // over 6.4M/4
    if (idx >= N_NODES * IN_CH / 4) return;
    float4 v = ((const float4*)x)[idx];
    __half2 h0 = __floats2half2_rn(v.x, v.y);
    __half2 h1 = __floats2half2_rn(v.z, v.w);
    ((uint2*)g_ah)[idx] = make_uint2(*(uint32_t*)&h0, *(uint32_t*)&h1);
}

__global__ void k_prep_b(const float* __restrict__ W) {
    int idx = blockIdx.x * blockDim.x + threadIdx.x;   // over 512*128
    if (idx >= F1 * IN_CH) return;
    int n = idx & (F1 - 1);
    int k = idx >> 9;
    g_bh[n * IN_CH + k] = __float2half_rn(W[k * F1 + n]);  // coalesced read
}

// ---------------- mma.sync GEMM: h1 = X @ W1  (+ fused attention scores) -----
// Grid (391, 4). CTA tile M=128 x N=128, full K=128 loaded up-front via
// cp.async (max MLP, no stage barriers). 8 warps as 4(M) x 2(N).
#define AS_STRIDE 136             // halves per row (272B: 16B-aligned, 8-row conflict-free)
#define TILE_BYTES_SM (128 * AS_STRIDE * 2)      // 34816
#define GEMM_SMEM (2 * TILE_BYTES_SM + 1024)     // A + B + scs

__global__ void __launch_bounds__(256) k_gemm_mma(
        const float* __restrict__ asrc, const float* __restrict__ adst) {
    extern __shared__ char dyn[];
    uint32_t sA = smem_u32(dyn);
    uint32_t sB = sA + TILE_BYTES_SM;
    float* scs = (float*)(dyn + 2 * TILE_BYTES_SM);  // [0,128) a_src, [128,256) a_dst

    int tid = threadIdx.x;
    int lane = tid & 31, wid = tid >> 5;
    int wm = wid & 3, wn = wid >> 2;
    int bm = blockIdx.x * 128;
    int nb = blockIdx.y;                 // N block: cols [nb*128, nb*128+128)

    // load full A (128x128 halves) and B tile via cp.async
    #pragma unroll
    for (int it = 0; it < 8; it++) {
        int idx = tid + it * 256;        // 0..2047
        int r = idx >> 4, c = idx & 15;
        int grow = bm + r;
        int ok = grow < N_NODES;
        const void* gp = g_ah + (size_t)(ok ? grow : 0) * IN_CH + c * 8;
        cp16(sA + (uint32_t)(r * AS_STRIDE + c * 8) * 2, gp, ok ? 16u : 0u);
    }
    #pragma unroll
    for (int it = 0; it < 8; it++) {
        int idx = tid + it * 256;
        int r = idx >> 4, c = idx & 15;
        const void* gp = g_bh + (size_t)(nb * 128 + r) * IN_CH + c * 8;
        cp16(sB + (uint32_t)(r * AS_STRIDE + c * 8) * 2, gp, 16u);
    }
    asm volatile("cp.async.commit_group;" ::: "memory");

    scs[tid] = (tid < 128) ? asrc[nb * 128 + tid] : adst[nb * 128 + tid - 128];

    float acc[2][8][4];
    #pragma unroll
    for (int i = 0; i < 2; i++)
        #pragma unroll
        for (int j = 0; j < 8; j++)
            #pragma unroll
            for (int q = 0; q < 4; q++) acc[i][j][q] = 0.f;

    uint32_t a_off0 = (uint32_t)((wm * 32 + (lane & 15)) * AS_STRIDE +
                                 (lane >> 4) * 8) * 2;
    uint32_t b_off0 = (uint32_t)(((lane >> 4) * 8 + (lane & 7)) * AS_STRIDE +
                                 ((lane >> 3) & 1) * 8) * 2;

    asm volatile("cp.async.wait_group 0;" ::: "memory");
    __syncthreads();

    #pragma unroll
    for (int ks = 0; ks < 8; ks++) {
        uint32_t af[2][4], bf[4][4];
        #pragma unroll
        for (int mt = 0; mt < 2; mt++)
            ldm_x4(af[mt], sA + a_off0 +
                   (uint32_t)(mt * 16 * AS_STRIDE + ks * 16) * 2);
        #pragma unroll
        for (int np = 0; np < 4; np++)
            ldm_x4(bf[np], sB + b_off0 +
                   (uint32_t)((wn * 64 + np * 16) * AS_STRIDE + ks * 16) * 2);
        #pragma unroll
        for (int mt = 0; mt < 2; mt++)
            #pragma unroll
            for (int np = 0; np < 4; np++) {
                mma_fp16(acc[mt][np * 2 + 0], af[mt], &bf[np][0]);
                mma_fp16(acc[mt][np * 2 + 1], af[mt], &bf[np][2]);
            }
    }

    // ---- epilogue: store h1 (fp16) + fused per-head attention scores --------
    int ql = lane & 3, qr = lane >> 2;
    int head = nb * 2 + wn;

    #pragma unroll
    for (int mt = 0; mt < 2; mt++) {
        int row0 = bm + wm * 32 + mt * 16 + qr;
        float sa0 = 0.f, sd0 = 0.f, sa8 = 0.f, sd8 = 0.f;
        #pragma unroll
        for (int nt = 0; nt < 8; nt++) {
            float d0 = acc[mt][nt][0], d1 = acc[mt][nt][1];
            float d2 = acc[mt][nt][2], d3 = acc[mt][nt][3];
            int cw = wn * 64 + nt * 8 + ql * 2;
            float v0 = scs[cw], v1 = scs[cw + 1];
            float u0 = scs[128 + cw], u1 = scs[128 + cw + 1];
            sa0 += d0 * v0 + d1 * v1;
            sd0 += d0 * u0 + d1 * u1;
            sa8 += d2 * v0 + d3 * v1;
            sd8 += d2 * u0 + d3 * u1;
            int col = nb * 128 + cw;
            if (row0 < N_NODES)
                *(__half2*)(g_h1h + (size_t)row0 * F1 + col) =
                    __floats2half2_rn(d0, d1);
            if (row0 + 8 < N_NODES)
                *(__half2*)(g_h1h + (size_t)(row0 + 8) * F1 + col) =
                    __floats2half2_rn(d2, d3);
        }
        #pragma unroll
        for (int o = 1; o <= 2; o <<= 1) {
            sa0 += __shfl_xor_sync(0xffffffffu, sa0, o);
            sd0 += __shfl_xor_sync(0xffffffffu, sd0, o);
            sa8 += __shfl_xor_sync(0xffffffffu, sa8, o);
            sd8 += __shfl_xor_sync(0xffffffffu, sd8, o);
        }
        if (ql == 0) {
            if (row0 < N_NODES) {
                g_as1[row0 * H1 + head] = sa0;
                g_ad1[row0 * H1 + head] = sd0;
            }
            if (row0 + 8 < N_NODES) {
                g_as1[(row0 + 8) * H1 + head] = sa8;
                g_ad1[(row0 + 8) * H1 + head] = sd8;
            }
        }
    }
}

// ---- layer-1 softmax + aggregation + bias + elu + FUSED layer-2 projection --
// 4 nodes per 256-thread block; 64-thread group per node, thread owns 8
// channels (one head), uint4 (16B) feature loads. Per 64-edge chunk:
//   phase 1: thread-per-edge computes the 8 head weights into smem
//   phase 2: streaming gather with addresses/weights from smem (high MLP).
__global__ void __launch_bounds__(256) k_agg1(const float* __restrict__ b1,
                                              const float* __restrict__ W2,
                                              const float* __restrict__ asrc2,
                                              const float* __restrict__ adst2) {
    __shared__ int   ssrc[4][64];
    __shared__ float sw[4][64][8];
    __shared__ float sadn[4][8];
    __shared__ float red[4][2][2];
    __shared__ int   smaxd;

    int tid = threadIdx.x;
    int g = tid >> 6;          // node group 0..3
    int t = tid & 63;          // thread in group
    int n = blockIdx.x * 4 + g;          // 50000 = 12500*4, always valid
    int ht = t >> 3;           // head owned by this thread

    int start = g_off[n];
    int deg = g_off[n + 1] - start;
    if (t < 8) sadn[g][t] = g_ad1[n * H1 + t];
    if (tid == 0) smaxd = 0;
    __syncthreads();
    if (t == 0) atomicMax(&smaxd, deg);
    __syncthreads();
    int maxdeg = smaxd;

    float acc[8] = {0.f, 0.f, 0.f, 0.f, 0.f, 0.f, 0.f, 0.f};
    float den = 0.f;
    const uint4* h8 = (const uint4*)g_h1h;   // 8 halves per uint4, row=64 uint4

    for (int c0 = 0; c0 < maxdeg; c0 += 64) {
        int clen = deg - c0;
        clen = (clen > 64) ? 64 : clen;
        if (t < clen) {
            int src = g_csr_src[start + c0 + t];
            ssrc[g][t] = src;
            float4 s01 = *(const float4*)(g_as1 + src * H1);
            float4 s45 = *(const float4*)(g_as1 + src * H1 + 4);
            float es[8] = {s01.x, s01.y, s01.z, s01.w,
                           s45.x, s45.y, s45.z, s45.w};
            float wv[8];
            #pragma unroll
            for (int h = 0; h < 8; h++) {
                float e = es[h] + sadn[g][h];
                e = (e > 0.f) ? e : NEG_SLOPE * e;
                wv[h] = __expf(e);
            }
            *(float4*)&sw[g][t][0] = make_float4(wv[0], wv[1], wv[2], wv[3]);
            *(float4*)&sw[g][t][4] = make_float4(wv[4], wv[5], wv[6], wv[7]);
        }
        __syncthreads();

        int jj = 0;
        for (; jj + 2 <= clen; jj += 2) {
            int s0 = ssrc[g][jj], s1 = ssrc[g][jj + 1];
            float w0 = sw[g][jj][ht], w1 = sw[g][jj + 1][ht];
            uint4 v0 = h8[(size_t)s0 * 64 + t];
            uint4 v1 = h8[(size_t)s1 * 64 + t];
            den += w0 + w1;
            const __half2* p0 = (const __half2*)&v0;
            const __half2* p1 = (const __half2*)&v1;
            #pragma unroll
            for (int q = 0; q < 4; q++) {
                float2 f0 = __half22float2(p0[q]);
                float2 f1 = __half22float2(p1[q]);
                acc[q * 2 + 0] += w0 * f0.x + w1 * f1.x;
                acc[q * 2 + 1] += w0 * f0.y + w1 * f1.y;
            }
        }
        if (jj < clen) {
            int s0 = ssrc[g][jj];
            float w0 = sw[g][jj][ht];
            uint4 v0 = h8[(size_t)s0 * 64 + t];
            den += w0;
            const __half2* p0 = (const __half2*)&v0;
            #pragma unroll
            for (int q = 0; q < 4; q++) {
                float2 f0 = __half22float2(p0[q]);
                acc[q * 2 + 0] += w0 * f0.x;
                acc[q * 2 + 1] += w0 * f0.y;
            }
        }
        __syncthreads();   // protect sw/ssrc reuse next chunk
    }

    // bias + ELU + fused 512->2 projection
    int c = t * 8;
    float4 bv0 = *(const float4*)(b1 + c);
    float4 bv1 = *(const float4*)(b1 + c + 4);
    float bvs[8] = {bv0.x, bv0.y, bv0.z, bv0.w, bv1.x, bv1.y, bv1.z, bv1.w};
    float inv = 1.f / den;
    float p0 = 0.f, p1 = 0.f;
    #pragma unroll
    for (int q = 0; q < 8; q++) {
        float o = acc[q] * inv + bvs[q];
        o = (o > 0.f) ? o : (__expf(o) - 1.f);
        p0 += o * W2[(c + q) * 2];
        p1 += o * W2[(c + q) * 2 + 1];
    }
    #pragma unroll
    for (int o = 16; o; o >>= 1) {
        p0 += __shfl_xor_sync(0xffffffffu, p0, o);
        p1 += __shfl_xor_sync(0xffffffffu, p1, o);
    }
    if ((t & 31) == 0) { red[g][t >> 5][0] = p0; red[g][t >> 5][1] = p1; }
    __syncthreads();
    if (t == 0) {
        float h20 = red[g][0][0] + red[g][1][0];
        float h21 = red[g][0][1] + red[g][1][1];
        g_h2[n * 2 + 0] = h20;
        g_h2[n * 2 + 1] = h21;
        g_as2[n] = h20 * asrc2[0] + h21 * asrc2[1];
        g_ad2[n] = h20 * adst2[0] + h21 * adst2[1];
    }
}

// ---------------- layer-2 softmax + aggregation (warp per node) -------------
__global__ void k_agg2(const float* __restrict__ b2, float* __restrict__ out) {
    int gw = (blockIdx.x * blockDim.x + threadIdx.x) >> 5;
    int lane = threadIdx.x & 31;
    if (gw >= N_NODES) return;
    int start = g_off[gw], end = g_off[gw + 1];
    float adn = g_ad2[gw];

    float den = 0.f, a0 = 0.f, a1 = 0.f;
    for (int j = start + lane; j < end; j += 32) {
        int src = g_csr_src[j];
        float e = g_as2[src] + adn;
        e = (e > 0.f) ? e : NEG_SLOPE * e;
        float w = __expf(e);
        den += w;
        a0 += w * g_h2[src * 2 + 0];
        a1 += w * g_h2[src * 2 + 1];
    }
    #pragma unroll
    for (int off = 16; off; off >>= 1) {
        den += __shfl_xor_sync(0xffffffffu, den, off);
        a0  += __shfl_xor_sync(0xffffffffu, a0, off);
        a1  += __shfl_xor_sync(0xffffffffu, a1, off);
    }
    if (lane == 0) {
        float inv = 1.f / den;
        out[gw * 2 + 0] = a0 * inv + b2[0];
        out[gw * 2 + 1] = a1 * inv + b2[1];
    }
}

// ---------------- launcher ---------------------------------------------------
extern "C" void kernel_launch(void* const* d_in, const int* in_sizes, int n_in,
                              void* d_out, int out_size) {
    const float* x      = (const float*)d_in[0];
    const int*   ei     = (const int*)  d_in[1];
    const float* W1     = (const float*)d_in[2];
    const float* a_src1 = (const float*)d_in[3];
    const float* a_dst1 = (const float*)d_in[4];
    const float* b1     = (const float*)d_in[5];
    const float* W2     = (const float*)d_in[6];
    const float* a_src2 = (const float*)d_in[7];
    const float* a_dst2 = (const float*)d_in[8];
    const float* b2     = (const float*)d_in[9];
    float* out = (float*)d_out;

    static int configured = 0;
    if (!configured) {
        cudaFuncSetAttribute(k_gemm_mma,
                             cudaFuncAttributeMaxDynamicSharedMemorySize,
                             GEMM_SMEM);
        configured = 1;
    }

    // independent prep + GEMM path (slot 4 = k_gemm_mma for ncu)
    k_prep_a<<<(N_NODES * IN_CH / 4 + 255) / 256, 256>>>(x);
    k_prep_b<<<(F1 * IN_CH + 255) / 256, 256>>>(W1);
    k_count<<<(N_EDGES + 255) / 256, 256>>>(ei);
    dim3 gg((N_NODES + 127) / 128, 4);
    k_gemm_mma<<<gg, 256, GEMM_SMEM>>>(a_src1, a_dst1);

    // CSR finish
    k_scan<<<1, 1024>>>();
    k_scatter<<<(ET + 255) / 256, 256>>>(ei);

    // layer-1 aggregation fused with layer-2 feature projection
    k_agg1<<<N_NODES / 4, 256>>>(b1, W2, a_src2, a_dst2);

    // layer 2 aggregation -> output
    k_agg2<<<(N_NODES + 7) / 8, 256>>>(b2, out);
}